// round 1
// baseline (speedup 1.0000x reference)
#include <cuda_runtime.h>

// Problem constants
#define R_TOTAL   327680          // N*T*VN rows
#define BTOT      32768           // N*T graph items
#define NB        8               // items per block in main kernel
#define ROWS      (NB*10)         // 80 rows per block
#define NBLK_STATS 2048
#define BN_EPS    1e-5f

// Scratch (allocation-free): partial sums + final BN affine params
__device__ float g_psum[NBLK_STATS * 128];
__device__ float g_psq [NBLK_STATS * 128];
__device__ float g_scale[128];
__device__ float g_shift[128];

// ---------------------------------------------------------------------------
// Kernel 1: per-channel sum / sumsq partials over all 327680 rows
// Thread t handles channels 4*(t&31)..+3 (float4), row slot t>>5 (8 rows/blk/iter)
// ---------------------------------------------------------------------------
__global__ void __launch_bounds__(256) stats_kernel(const float4* __restrict__ x4) {
    __shared__ float s_sum[256][4];
    __shared__ float s_sq [256][4];
    const int tid  = threadIdx.x;
    const int lane = tid & 31;
    const int slot = tid >> 5;

    float4 sum = make_float4(0.f, 0.f, 0.f, 0.f);
    float4 sq  = make_float4(0.f, 0.f, 0.f, 0.f);

    int row = blockIdx.x * 8 + slot;
    const int stride = NBLK_STATS * 8;          // 16384 rows per sweep
    #pragma unroll 4
    for (int it = 0; it < R_TOTAL / stride; ++it) {   // exactly 20 iters
        float4 v = x4[(size_t)row * 32 + lane];
        sum.x += v.x; sum.y += v.y; sum.z += v.z; sum.w += v.w;
        sq.x  += v.x * v.x; sq.y += v.y * v.y; sq.z += v.z * v.z; sq.w += v.w * v.w;
        row += stride;
    }
    s_sum[tid][0] = sum.x; s_sum[tid][1] = sum.y; s_sum[tid][2] = sum.z; s_sum[tid][3] = sum.w;
    s_sq [tid][0] = sq.x;  s_sq [tid][1] = sq.y;  s_sq [tid][2] = sq.z;  s_sq [tid][3] = sq.w;
    __syncthreads();

    for (int off = 128; off >= 32; off >>= 1) {
        if (tid < off) {
            #pragma unroll
            for (int j = 0; j < 4; ++j) {
                s_sum[tid][j] += s_sum[tid + off][j];
                s_sq [tid][j] += s_sq [tid + off][j];
            }
        }
        __syncthreads();
    }
    if (tid < 32) {
        #pragma unroll
        for (int j = 0; j < 4; ++j) {
            g_psum[blockIdx.x * 128 + tid * 4 + j] = s_sum[tid][j];
            g_psq [blockIdx.x * 128 + tid * 4 + j] = s_sq [tid][j];
        }
    }
}

// ---------------------------------------------------------------------------
// Kernel 2: reduce partials -> scale = gamma*rsqrt(var+eps), shift = beta - mean*scale
// ---------------------------------------------------------------------------
__global__ void finalize_kernel(const float* __restrict__ gamma,
                                const float* __restrict__ beta) {
    const int c = threadIdx.x;            // 128 threads
    float s = 0.f, q = 0.f;
    for (int b = 0; b < NBLK_STATS; ++b) {
        s += g_psum[b * 128 + c];
        q += g_psq [b * 128 + c];
    }
    const float inv_n = 1.0f / (float)R_TOTAL;
    float mean = s * inv_n;
    float var  = q * inv_n - mean * mean;          // biased, matches jnp.var / torch BN
    float sc   = gamma[c] * rsqrtf(var + BN_EPS);
    g_scale[c] = sc;
    g_shift[c] = beta[c] - mean * sc;
}

// ---------------------------------------------------------------------------
// Kernel 3: fused normalize -> QKV -> masked attention -> out-proj
// Grid 4096 blocks x 256 threads, ~194 KB dynamic smem (1 block/SM)
// smem floats: sy 10240 | sqkv 30720 | swb 8192 | scale 128 | shift 128 | mask 128 | bout 128
// ---------------------------------------------------------------------------
#define SMEM_FLOATS (10240 + 30720 + 8192 + 512)
#define SMEM_BYTES  (SMEM_FLOATS * 4)

__global__ void __launch_bounds__(256, 1)
main_kernel(const float* __restrict__ x,
            const float* __restrict__ w_qkv,
            const float* __restrict__ w_out,
            const float* __restrict__ b_out,
            const float* __restrict__ mask,
            float* __restrict__ out) {
    extern __shared__ float sm[];
    float* sy      = sm;                 // 80 x 128 (y, later attn_out)
    float* sqkv    = sy + 10240;         // 80 x 384
    float* swb     = sqkv + 30720;       // 64 x 128 weight K-half chunk
    float* s_scale = swb + 8192;
    float* s_shift = s_scale + 128;
    float* s_mask  = s_shift + 128;
    float* s_bout  = s_mask + 128;

    const int tid = threadIdx.x;
    const int tx  = tid & 31;            // column group (4 cols)
    const int ty  = tid >> 5;            // row group (10 rows)
    const int row0 = blockIdx.x * ROWS;

    if (tid < 128) {
        s_scale[tid] = g_scale[tid];
        s_shift[tid] = g_shift[tid];
        s_bout [tid] = b_out[tid];
    }
    if (tid < 100) s_mask[tid] = mask[tid];
    __syncthreads();

    // ---- Phase 1: load + BN-normalize x tile into sy -----------------------
    {
        const float4* x4 = (const float4*)x;
        const float4* sc4 = (const float4*)s_scale;
        const float4* sh4 = (const float4*)s_shift;
        #pragma unroll
        for (int f = tid; f < ROWS * 32; f += 256) {
            int r = f >> 5, c4 = f & 31;
            float4 v = x4[(size_t)(row0 + r) * 32 + c4];
            float4 sc = sc4[c4], sh = sh4[c4];
            v.x = fmaf(v.x, sc.x, sh.x);
            v.y = fmaf(v.y, sc.y, sh.y);
            v.z = fmaf(v.z, sc.z, sh.z);
            v.w = fmaf(v.w, sc.w, sh.w);
            *((float4*)&sy[r * 128 + c4 * 4]) = v;
        }
    }

    // ---- Phase 2: QKV GEMM (80x128 @ 128x384), N split q/k/v, K split halves
    for (int nc = 0; nc < 3; ++nc) {
        float4 acc[10];
        #pragma unroll
        for (int i = 0; i < 10; ++i) acc[i] = make_float4(0.f, 0.f, 0.f, 0.f);

        for (int kh = 0; kh < 2; ++kh) {
            __syncthreads();     // previous swb readers done (also covers sy write->read)
            #pragma unroll
            for (int f = tid; f < 64 * 32; f += 256) {
                int kk = f >> 5, c4 = f & 31;
                *((float4*)&swb[kk * 128 + c4 * 4]) =
                    *(const float4*)&w_qkv[(kh * 64 + kk) * 384 + nc * 128 + c4 * 4];
            }
            __syncthreads();

            const float* yr = sy + ty * 10 * 128 + kh * 64;
            #pragma unroll 4
            for (int kk = 0; kk < 64; ++kk) {
                float4 b = *(const float4*)&swb[kk * 128 + tx * 4];
                #pragma unroll
                for (int i = 0; i < 10; ++i) {
                    float a = yr[i * 128 + kk];
                    acc[i].x = fmaf(a, b.x, acc[i].x);
                    acc[i].y = fmaf(a, b.y, acc[i].y);
                    acc[i].z = fmaf(a, b.z, acc[i].z);
                    acc[i].w = fmaf(a, b.w, acc[i].w);
                }
            }
        }
        #pragma unroll
        for (int i = 0; i < 10; ++i)
            *((float4*)&sqkv[(ty * 10 + i) * 384 + nc * 128 + tx * 4]) = acc[i];
    }
    __syncthreads();   // sqkv complete; sy GEMM reads complete

    // ---- Phase 3: masked attention, writes attn_out into sy ----------------
    // 64 (item,head) pairs, 4 threads/pair, each thread owns rows i = sub+4k
    {
        const int pair = tid >> 2;          // 0..63
        const int sub  = tid & 3;
        const int li   = pair >> 3;         // item 0..7
        const int h    = pair & 7;          // head 0..7
        const float* qb = sqkv + li * 10 * 384 + h * 16;       // q cols [0,128)
        const float* kb = qb + 128;                            // k cols [128,256)
        const float* vb = qb + 256;                            // v cols [256,384)

        for (int i = sub; i < 10; i += 4) {
            float q[16];
            #pragma unroll
            for (int t = 0; t < 16; ++t) q[t] = qb[i * 384 + t];

            float d[10], m = -1e30f;
            #pragma unroll
            for (int j = 0; j < 10; ++j) {
                float s = 0.f;
                #pragma unroll
                for (int t = 0; t < 16; ++t) s = fmaf(q[t], kb[j * 384 + t], s);
                // multiplicative mask AFTER scaling: zeros stay zero, exp(0)=1 counts
                s = s * 0.25f * s_mask[i * 10 + j];
                d[j] = s;
                m = fmaxf(m, s);
            }
            float sum = 0.f;
            #pragma unroll
            for (int j = 0; j < 10; ++j) { d[j] = __expf(d[j] - m); sum += d[j]; }
            const float inv = 1.0f / sum;

            float o[16];
            #pragma unroll
            for (int t = 0; t < 16; ++t) o[t] = 0.f;
            #pragma unroll
            for (int j = 0; j < 10; ++j) {
                float a = d[j] * inv;
                #pragma unroll
                for (int t = 0; t < 16; ++t) o[t] = fmaf(a, vb[j * 384 + t], o[t]);
            }
            #pragma unroll
            for (int t = 0; t < 16; t += 4)
                *((float4*)&sy[(li * 10 + i) * 128 + h * 16 + t]) =
                    make_float4(o[t], o[t + 1], o[t + 2], o[t + 3]);
        }
    }
    __syncthreads();   // attn_out in sy complete

    // ---- Phase 4: out projection (80x128 @ 128x128) + bias -> global -------
    {
        float4 acc[10];
        #pragma unroll
        for (int i = 0; i < 10; ++i) acc[i] = make_float4(0.f, 0.f, 0.f, 0.f);

        for (int kh = 0; kh < 2; ++kh) {
            __syncthreads();
            #pragma unroll
            for (int f = tid; f < 64 * 32; f += 256) {
                int kk = f >> 5, c4 = f & 31;
                *((float4*)&swb[kk * 128 + c4 * 4]) =
                    *(const float4*)&w_out[(kh * 64 + kk) * 128 + c4 * 4];
            }
            __syncthreads();

            const float* yr = sy + ty * 10 * 128 + kh * 64;
            #pragma unroll 4
            for (int kk = 0; kk < 64; ++kk) {
                float4 b = *(const float4*)&swb[kk * 128 + tx * 4];
                #pragma unroll
                for (int i = 0; i < 10; ++i) {
                    float a = yr[i * 128 + kk];
                    acc[i].x = fmaf(a, b.x, acc[i].x);
                    acc[i].y = fmaf(a, b.y, acc[i].y);
                    acc[i].z = fmaf(a, b.z, acc[i].z);
                    acc[i].w = fmaf(a, b.w, acc[i].w);
                }
            }
        }
        const float4 bo = ((const float4*)s_bout)[tx];
        #pragma unroll
        for (int i = 0; i < 10; ++i) {
            float4 v = acc[i];
            v.x += bo.x; v.y += bo.y; v.z += bo.z; v.w += bo.w;
            *((float4*)&out[(size_t)(row0 + ty * 10 + i) * 128 + tx * 4]) = v;
        }
    }
}

// ---------------------------------------------------------------------------
extern "C" void kernel_launch(void* const* d_in, const int* in_sizes, int n_in,
                              void* d_out, int out_size) {
    const float* x     = (const float*)d_in[0];
    const float* gamma = (const float*)d_in[1];
    const float* beta  = (const float*)d_in[2];
    const float* w_qkv = (const float*)d_in[3];
    const float* w_out = (const float*)d_in[4];
    const float* b_out = (const float*)d_in[5];
    const float* mask  = (const float*)d_in[6];
    float* out = (float*)d_out;

    cudaFuncSetAttribute(main_kernel,
                         cudaFuncAttributeMaxDynamicSharedMemorySize, SMEM_BYTES);

    stats_kernel<<<NBLK_STATS, 256>>>((const float4*)x);
    finalize_kernel<<<1, 128>>>(gamma, beta);
    main_kernel<<<BTOT / NB, 256, SMEM_BYTES>>>(x, w_qkv, w_out, b_out, mask, out);
}

// round 2
// speedup vs baseline: 2.6356x; 2.6356x over previous
#include <cuda_runtime.h>

// ---------------------------------------------------------------------------
// Problem constants
#define R_TOTAL   327680          // N*T*VN rows
#define BTOT      32768           // N*T graph items
#define NB        8               // items per block in main kernel
#define ROWS      (NB*10)         // 80 rows per block -> 5 m-tiles of 16
#define NBLK_STATS 2048
#define BN_EPS    1e-5f

// Scratch (allocation-free)
__device__ float g_psum[NBLK_STATS * 128];
__device__ float g_psq [NBLK_STATS * 128];
__device__ float g_scale[128];
__device__ float g_shift[128];
// Pre-permuted weights in mma fragment order (tf32-rounded bits)
// wqkv: [48 n-tiles][16 ks][32 lanes][2]  ; wout: [16][16][32][2]
__device__ float g_wqkv_perm[48 * 16 * 32 * 2];
__device__ float g_wout_perm[16 * 16 * 32 * 2];

// ---------------------------------------------------------------------------
__device__ __forceinline__ unsigned tf32r(float f) {
    unsigned r;
    asm("cvt.rna.tf32.f32 %0, %1;" : "=r"(r) : "f"(f));
    return r;
}

__device__ __forceinline__ void mma_tf32(float& c0, float& c1, float& c2, float& c3,
                                         unsigned a0, unsigned a1, unsigned a2, unsigned a3,
                                         unsigned b0, unsigned b1) {
    asm volatile("mma.sync.aligned.m16n8k8.row.col.f32.tf32.tf32.f32 "
                 "{%0,%1,%2,%3}, {%4,%5,%6,%7}, {%8,%9}, {%0,%1,%2,%3};\n"
                 : "+f"(c0), "+f"(c1), "+f"(c2), "+f"(c3)
                 : "r"(a0), "r"(a1), "r"(a2), "r"(a3), "r"(b0), "r"(b1));
}

// ---------------------------------------------------------------------------
// Kernel 1: per-channel sum / sumsq partials (unchanged; 32us, 67% HBM)
// ---------------------------------------------------------------------------
__global__ void __launch_bounds__(256) stats_kernel(const float4* __restrict__ x4) {
    __shared__ float s_sum[256][4];
    __shared__ float s_sq [256][4];
    const int tid  = threadIdx.x;
    const int lane = tid & 31;
    const int slot = tid >> 5;

    float4 sum = make_float4(0.f, 0.f, 0.f, 0.f);
    float4 sq  = make_float4(0.f, 0.f, 0.f, 0.f);

    int row = blockIdx.x * 8 + slot;
    const int stride = NBLK_STATS * 8;
    #pragma unroll 4
    for (int it = 0; it < R_TOTAL / stride; ++it) {
        float4 v = x4[(size_t)row * 32 + lane];
        sum.x += v.x; sum.y += v.y; sum.z += v.z; sum.w += v.w;
        sq.x += v.x * v.x; sq.y += v.y * v.y; sq.z += v.z * v.z; sq.w += v.w * v.w;
        row += stride;
    }
    s_sum[tid][0] = sum.x; s_sum[tid][1] = sum.y; s_sum[tid][2] = sum.z; s_sum[tid][3] = sum.w;
    s_sq [tid][0] = sq.x;  s_sq [tid][1] = sq.y;  s_sq [tid][2] = sq.z;  s_sq [tid][3] = sq.w;
    __syncthreads();
    for (int off = 128; off >= 32; off >>= 1) {
        if (tid < off) {
            #pragma unroll
            for (int j = 0; j < 4; ++j) {
                s_sum[tid][j] += s_sum[tid + off][j];
                s_sq [tid][j] += s_sq [tid + off][j];
            }
        }
        __syncthreads();
    }
    if (tid < 32) {
        #pragma unroll
        for (int j = 0; j < 4; ++j) {
            g_psum[blockIdx.x * 128 + tid * 4 + j] = s_sum[tid][j];
            g_psq [blockIdx.x * 128 + tid * 4 + j] = s_sq [tid][j];
        }
    }
}

// ---------------------------------------------------------------------------
// Kernel 2: finalize BN affine params
// ---------------------------------------------------------------------------
__global__ void finalize_kernel(const float* __restrict__ gamma,
                                const float* __restrict__ beta) {
    const int c = threadIdx.x;
    float s = 0.f, q = 0.f;
    for (int b = 0; b < NBLK_STATS; ++b) {
        s += g_psum[b * 128 + c];
        q += g_psq [b * 128 + c];
    }
    const float inv_n = 1.0f / (float)R_TOTAL;
    float mean = s * inv_n;
    float var  = q * inv_n - mean * mean;
    float sc   = gamma[c] * rsqrtf(var + BN_EPS);
    g_scale[c] = sc;
    g_shift[c] = beta[c] - mean * sc;
}

// ---------------------------------------------------------------------------
// Kernel 2b: permute weights into mma B-fragment order (tf32 rounded)
// b0 = W[ks*8 + (l&3)][nt*8 + (l>>2)], b1 = +4 rows
// ---------------------------------------------------------------------------
__global__ void permute_weights(const float* __restrict__ wqkv,
                                const float* __restrict__ wout) {
    int idx = blockIdx.x * 256 + threadIdx.x;     // 49152 total
    {
        int t  = idx & 1;
        int l  = (idx >> 1) & 31;
        int ks = (idx >> 6) & 15;
        int nt = idx >> 10;                       // 0..47
        int k = ks * 8 + (l & 3) + t * 4;
        int n = nt * 8 + (l >> 2);
        g_wqkv_perm[idx] = __uint_as_float(tf32r(wqkv[k * 384 + n]));
    }
    if (idx < 16384) {
        int t  = idx & 1;
        int l  = (idx >> 1) & 31;
        int ks = (idx >> 6) & 15;
        int nt = idx >> 10;                       // 0..15
        int k = ks * 8 + (l & 3) + t * 4;
        int n = nt * 8 + (l >> 2);
        g_wout_perm[idx] = __uint_as_float(tf32r(wout[k * 128 + n]));
    }
}

// ---------------------------------------------------------------------------
// Kernel 3: fused BN-normalize -> QKV (tf32 mma) -> attention -> out-proj
// smem floats: sy_perm 10240 | qs 11264 | ks 11264 | vs 11264 | small 512
// ---------------------------------------------------------------------------
#define QKV_BLK   176                       // per (item,head) block stride (== 16 mod 32)
#define SMEM_FLOATS (10240 + 3 * 11264 + 512)
#define SMEM_BYTES  (SMEM_FLOATS * 4)

__global__ void __launch_bounds__(256, 1)
main_kernel(const float* __restrict__ x,
            const float* __restrict__ b_out,
            const float* __restrict__ mask,
            float* __restrict__ out) {
    extern __shared__ float sm[];
    float* sy      = sm;                  // 5 x 16 x 32 x 4 (A fragments, ks-XOR swizzled)
    float* qs      = sy + 10240;          // [li*8+h]*176 + i*16 + dh
    float* kvk     = qs + 11264;
    float* kvv     = kvk + 11264;
    float* s_scale = kvv + 11264;
    float* s_shift = s_scale + 128;
    float* s_mask  = s_shift + 128;
    float* s_bout  = s_mask + 128;

    const int tid  = threadIdx.x;
    const int lane = tid & 31;
    const int wrp  = tid >> 5;            // 0..7
    const int tig  = lane & 3;
    const int gid  = lane >> 2;
    const int row0 = blockIdx.x * ROWS;

    if (tid < 128) {
        s_scale[tid] = g_scale[tid];
        s_shift[tid] = g_shift[tid];
        s_bout [tid] = b_out[tid];
    }
    if (tid < 100) s_mask[tid] = mask[tid];
    __syncthreads();

    // ---- Phase 1: load + BN-normalize x into fragment-permuted sy ----------
    {
        const float4* x4  = (const float4*)x;
        const float4* sc4 = (const float4*)s_scale;
        const float4* sh4 = (const float4*)s_shift;
        #pragma unroll
        for (int f = tid; f < ROWS * 32; f += 256) {
            int r = f >> 5, c4 = f & 31;
            float4 v = x4[(size_t)(row0 + r) * 32 + c4];
            float4 sc = sc4[c4], sh = sh4[c4];
            float e0 = fmaf(v.x, sc.x, sh.x);
            float e1 = fmaf(v.y, sc.y, sh.y);
            float e2 = fmaf(v.z, sc.z, sh.z);
            float e3 = fmaf(v.w, sc.w, sh.w);
            int m = r >> 4, rr = r & 15, ks = c4 >> 1, kx = ks & 7;
            int slot  = (rr >> 3) + 2 * (c4 & 1);
            int lane0 = (rr & 7) * 4;
            int base  = (m * 16 + ks) * 32;
            sy[(base + ((lane0 + 0) ^ kx)) * 4 + slot] = __uint_as_float(tf32r(e0));
            sy[(base + ((lane0 + 1) ^ kx)) * 4 + slot] = __uint_as_float(tf32r(e1));
            sy[(base + ((lane0 + 2) ^ kx)) * 4 + slot] = __uint_as_float(tf32r(e2));
            sy[(base + ((lane0 + 3) ^ kx)) * 4 + slot] = __uint_as_float(tf32r(e3));
        }
    }
    __syncthreads();

    // ---- Phase 2: QKV GEMM via tf32 mma. Warp w owns n-tiles 6w..6w+5 ------
    {
        float acc[5][6][4];
        #pragma unroll
        for (int m = 0; m < 5; ++m)
            #pragma unroll
            for (int n = 0; n < 6; ++n)
                #pragma unroll
                for (int e = 0; e < 4; ++e) acc[m][n][e] = 0.f;

        const uint2* gb = (const uint2*)g_wqkv_perm;
        const int nt0 = 6 * wrp;

        #pragma unroll 4
        for (int ks = 0; ks < 16; ++ks) {
            uint2 b[6];
            #pragma unroll
            for (int n = 0; n < 6; ++n)
                b[n] = __ldg(&gb[((nt0 + n) * 16 + ks) * 32 + lane]);
            const int kx = ks & 7;
            #pragma unroll
            for (int m = 0; m < 5; ++m) {
                float4 a = *(const float4*)&sy[((m * 16 + ks) * 32 + (lane ^ kx)) * 4];
                unsigned a0 = __float_as_uint(a.x), a1 = __float_as_uint(a.y);
                unsigned a2 = __float_as_uint(a.z), a3 = __float_as_uint(a.w);
                #pragma unroll
                for (int n = 0; n < 6; ++n)
                    mma_tf32(acc[m][n][0], acc[m][n][1], acc[m][n][2], acc[m][n][3],
                             a0, a1, a2, a3, b[n].x, b[n].y);
            }
        }

        // scatter C into q/k/v blocked layout
        #pragma unroll
        for (int m = 0; m < 5; ++m)
            #pragma unroll
            for (int n = 0; n < 6; ++n) {
                int nt = nt0 + n;
                int Cn = nt * 8 + 2 * tig;            // even, 0..382
                int sel = Cn >> 7;
                int cc  = Cn & 127;
                int h   = cc >> 4;
                int dh  = cc & 15;
                float* dst = (sel == 0) ? qs : (sel == 1) ? kvk : kvv;
                int R0 = m * 16 + gid;
                int li0 = R0 / 10, i0 = R0 - li0 * 10;
                *(float2*)&dst[(li0 * 8 + h) * QKV_BLK + i0 * 16 + dh] =
                    make_float2(acc[m][n][0], acc[m][n][1]);
                int R1 = R0 + 8;
                int li1 = R1 / 10, i1 = R1 - li1 * 10;
                *(float2*)&dst[(li1 * 8 + h) * QKV_BLK + i1 * 16 + dh] =
                    make_float2(acc[m][n][2], acc[m][n][3]);
            }
    }
    __syncthreads();

    // ---- Phase 3: masked attention (dh-split, shfl reduce) ----------------
    // li = warp, h = (tid>>2)&7, sub = tid&3 owns dims [4*sub, 4*sub+4)
    {
        const int li  = wrp;
        const int h   = (tid >> 2) & 7;
        const int sub = tid & 3;
        const int blk = (li * 8 + h) * QKV_BLK + sub * 4;

        float4 qv[10], kv[10], vv[10];
        #pragma unroll
        for (int j = 0; j < 10; ++j) {
            qv[j] = *(const float4*)&qs [blk + j * 16];
            kv[j] = *(const float4*)&kvk[blk + j * 16];
            vv[j] = *(const float4*)&kvv[blk + j * 16];
        }

        #pragma unroll
        for (int i = 0; i < 10; ++i) {
            float d[10], mx = -1e30f;
            #pragma unroll
            for (int j = 0; j < 10; ++j) {
                float p = qv[i].x * kv[j].x + qv[i].y * kv[j].y
                        + qv[i].z * kv[j].z + qv[i].w * kv[j].w;
                p += __shfl_xor_sync(0xffffffffu, p, 1);
                p += __shfl_xor_sync(0xffffffffu, p, 2);
                p = p * 0.25f * s_mask[i * 10 + j];
                d[j] = p;
                mx = fmaxf(mx, p);
            }
            float ssum = 0.f;
            #pragma unroll
            for (int j = 0; j < 10; ++j) { d[j] = __expf(d[j] - mx); ssum += d[j]; }
            const float inv = 1.0f / ssum;
            float o0 = 0.f, o1 = 0.f, o2 = 0.f, o3 = 0.f;
            #pragma unroll
            for (int j = 0; j < 10; ++j) {
                float a = d[j] * inv;
                o0 = fmaf(a, vv[j].x, o0);
                o1 = fmaf(a, vv[j].y, o1);
                o2 = fmaf(a, vv[j].z, o2);
                o3 = fmaf(a, vv[j].w, o3);
            }
            // scatter into sy (fragment-permuted, same XOR swizzle)
            int R = li * 10 + i;
            int m = R >> 4, rr = R & 15;
            int C0 = h * 16 + sub * 4;
            int ks = C0 >> 3, kx = ks & 7;
            int slot  = (rr >> 3) + 2 * (sub & 1);
            int lane0 = (rr & 7) * 4;
            int base  = (m * 16 + ks) * 32;
            sy[(base + ((lane0 + 0) ^ kx)) * 4 + slot] = __uint_as_float(tf32r(o0));
            sy[(base + ((lane0 + 1) ^ kx)) * 4 + slot] = __uint_as_float(tf32r(o1));
            sy[(base + ((lane0 + 2) ^ kx)) * 4 + slot] = __uint_as_float(tf32r(o2));
            sy[(base + ((lane0 + 3) ^ kx)) * 4 + slot] = __uint_as_float(tf32r(o3));
        }
    }
    __syncthreads();

    // ---- Phase 4: out projection via tf32 mma. Warp w owns n-tiles 2w,2w+1 -
    {
        float acc[5][2][4];
        #pragma unroll
        for (int m = 0; m < 5; ++m)
            #pragma unroll
            for (int n = 0; n < 2; ++n)
                #pragma unroll
                for (int e = 0; e < 4; ++e) acc[m][n][e] = 0.f;

        const uint2* gb = (const uint2*)g_wout_perm;
        const int nt0 = 2 * wrp;

        #pragma unroll 4
        for (int ks = 0; ks < 16; ++ks) {
            uint2 b[2];
            #pragma unroll
            for (int n = 0; n < 2; ++n)
                b[n] = __ldg(&gb[((nt0 + n) * 16 + ks) * 32 + lane]);
            const int kx = ks & 7;
            #pragma unroll
            for (int m = 0; m < 5; ++m) {
                float4 a = *(const float4*)&sy[((m * 16 + ks) * 32 + (lane ^ kx)) * 4];
                unsigned a0 = __float_as_uint(a.x), a1 = __float_as_uint(a.y);
                unsigned a2 = __float_as_uint(a.z), a3 = __float_as_uint(a.w);
                #pragma unroll
                for (int n = 0; n < 2; ++n)
                    mma_tf32(acc[m][n][0], acc[m][n][1], acc[m][n][2], acc[m][n][3],
                             a0, a1, a2, a3, b[n].x, b[n].y);
            }
        }

        #pragma unroll
        for (int m = 0; m < 5; ++m)
            #pragma unroll
            for (int n = 0; n < 2; ++n) {
                int col = (nt0 + n) * 8 + 2 * tig;
                float b0 = s_bout[col], b1 = s_bout[col + 1];
                int R0 = m * 16 + gid;
                *(float2*)&out[(size_t)(row0 + R0) * 128 + col] =
                    make_float2(acc[m][n][0] + b0, acc[m][n][1] + b1);
                *(float2*)&out[(size_t)(row0 + R0 + 8) * 128 + col] =
                    make_float2(acc[m][n][2] + b0, acc[m][n][3] + b1);
            }
    }
}

// ---------------------------------------------------------------------------
extern "C" void kernel_launch(void* const* d_in, const int* in_sizes, int n_in,
                              void* d_out, int out_size) {
    const float* x     = (const float*)d_in[0];
    const float* gamma = (const float*)d_in[1];
    const float* beta  = (const float*)d_in[2];
    const float* w_qkv = (const float*)d_in[3];
    const float* w_out = (const float*)d_in[4];
    const float* b_out = (const float*)d_in[5];
    const float* mask  = (const float*)d_in[6];
    float* out = (float*)d_out;

    cudaFuncSetAttribute(main_kernel,
                         cudaFuncAttributeMaxDynamicSharedMemorySize, SMEM_BYTES);

    permute_weights<<<192, 256>>>(w_qkv, w_out);
    stats_kernel<<<NBLK_STATS, 256>>>((const float4*)x);
    finalize_kernel<<<1, 128>>>(gamma, beta);
    main_kernel<<<BTOT / NB, 256, SMEM_BYTES>>>(x, b_out, mask, out);
}

// round 3
// speedup vs baseline: 2.9209x; 1.1083x over previous
#include <cuda_runtime.h>

// ---------------------------------------------------------------------------
// Problem constants
#define R_TOTAL   327680          // N*T*VN rows
#define BTOT      32768           // N*T graph items
#define NB        4               // items per block in main kernel
#define ROWS      (NB*10)         // 40 rows per block -> 3 m-tiles (48, 8 pad)
#define MT        3               // m-tiles
#define NBLK_STATS 2048
#define BN_EPS    1e-5f

// Scratch (allocation-free)
__device__ float g_psum[NBLK_STATS * 128];
__device__ float g_psq [NBLK_STATS * 128];
__device__ float g_scale[128];
__device__ float g_shift[128];
// Pre-permuted weights in mma fragment order (tf32-rounded bits)
__device__ float g_wqkv_perm[48 * 16 * 32 * 2];
__device__ float g_wout_perm[16 * 16 * 32 * 2];

// ---------------------------------------------------------------------------
__device__ __forceinline__ unsigned tf32r(float f) {
    unsigned r;
    asm("cvt.rna.tf32.f32 %0, %1;" : "=r"(r) : "f"(f));
    return r;
}

__device__ __forceinline__ void mma_tf32(float& c0, float& c1, float& c2, float& c3,
                                         unsigned a0, unsigned a1, unsigned a2, unsigned a3,
                                         unsigned b0, unsigned b1) {
    asm volatile("mma.sync.aligned.m16n8k8.row.col.f32.tf32.tf32.f32 "
                 "{%0,%1,%2,%3}, {%4,%5,%6,%7}, {%8,%9}, {%0,%1,%2,%3};\n"
                 : "+f"(c0), "+f"(c1), "+f"(c2), "+f"(c3)
                 : "r"(a0), "r"(a1), "r"(a2), "r"(a3), "r"(b0), "r"(b1));
}

// ---------------------------------------------------------------------------
// Kernel 1: per-channel sum / sumsq partials
// ---------------------------------------------------------------------------
__global__ void __launch_bounds__(256) stats_kernel(const float4* __restrict__ x4) {
    __shared__ float s_sum[256][4];
    __shared__ float s_sq [256][4];
    const int tid  = threadIdx.x;
    const int lane = tid & 31;
    const int slot = tid >> 5;

    float4 sum = make_float4(0.f, 0.f, 0.f, 0.f);
    float4 sq  = make_float4(0.f, 0.f, 0.f, 0.f);

    int row = blockIdx.x * 8 + slot;
    const int stride = NBLK_STATS * 8;
    #pragma unroll 4
    for (int it = 0; it < R_TOTAL / stride; ++it) {
        float4 v = x4[(size_t)row * 32 + lane];
        sum.x += v.x; sum.y += v.y; sum.z += v.z; sum.w += v.w;
        sq.x += v.x * v.x; sq.y += v.y * v.y; sq.z += v.z * v.z; sq.w += v.w * v.w;
        row += stride;
    }
    s_sum[tid][0] = sum.x; s_sum[tid][1] = sum.y; s_sum[tid][2] = sum.z; s_sum[tid][3] = sum.w;
    s_sq [tid][0] = sq.x;  s_sq [tid][1] = sq.y;  s_sq [tid][2] = sq.z;  s_sq [tid][3] = sq.w;
    __syncthreads();
    for (int off = 128; off >= 32; off >>= 1) {
        if (tid < off) {
            #pragma unroll
            for (int j = 0; j < 4; ++j) {
                s_sum[tid][j] += s_sum[tid + off][j];
                s_sq [tid][j] += s_sq [tid + off][j];
            }
        }
        __syncthreads();
    }
    if (tid < 32) {
        #pragma unroll
        for (int j = 0; j < 4; ++j) {
            g_psum[blockIdx.x * 128 + tid * 4 + j] = s_sum[tid][j];
            g_psq [blockIdx.x * 128 + tid * 4 + j] = s_sq [tid][j];
        }
    }
}

// ---------------------------------------------------------------------------
// Kernel 2: finalize BN affine params (parallel: 8 slices per channel)
// ---------------------------------------------------------------------------
__global__ void __launch_bounds__(1024) finalize_kernel(const float* __restrict__ gamma,
                                                        const float* __restrict__ beta) {
    __shared__ float r_sum[1024];
    __shared__ float r_sq [1024];
    const int tid = threadIdx.x;
    const int c = tid & 127;
    const int s = tid >> 7;              // 0..7
    float sum = 0.f, sq = 0.f;
    #pragma unroll 8
    for (int b = s; b < NBLK_STATS; b += 8) {
        sum += g_psum[b * 128 + c];
        sq  += g_psq [b * 128 + c];
    }
    r_sum[tid] = sum;
    r_sq [tid] = sq;
    __syncthreads();
    if (tid < 128) {
        float S = 0.f, Q = 0.f;
        #pragma unroll
        for (int j = 0; j < 8; ++j) { S += r_sum[j * 128 + c]; Q += r_sq[j * 128 + c]; }
        const float inv_n = 1.0f / (float)R_TOTAL;
        float mean = S * inv_n;
        float var  = Q * inv_n - mean * mean;
        float sc   = gamma[c] * rsqrtf(var + BN_EPS);
        g_scale[c] = sc;
        g_shift[c] = beta[c] - mean * sc;
    }
}

// ---------------------------------------------------------------------------
// Kernel 2b: permute weights into mma B-fragment order (tf32 rounded)
// ---------------------------------------------------------------------------
__global__ void permute_weights(const float* __restrict__ wqkv,
                                const float* __restrict__ wout) {
    int idx = blockIdx.x * 256 + threadIdx.x;     // 49152 total
    {
        int t  = idx & 1;
        int l  = (idx >> 1) & 31;
        int ks = (idx >> 6) & 15;
        int nt = idx >> 10;                       // 0..47
        int k = ks * 8 + (l & 3) + t * 4;
        int n = nt * 8 + (l >> 2);
        g_wqkv_perm[idx] = __uint_as_float(tf32r(wqkv[k * 384 + n]));
    }
    if (idx < 16384) {
        int t  = idx & 1;
        int l  = (idx >> 1) & 31;
        int ks = (idx >> 6) & 15;
        int nt = idx >> 10;                       // 0..15
        int k = ks * 8 + (l & 3) + t * 4;
        int n = nt * 8 + (l >> 2);
        g_wout_perm[idx] = __uint_as_float(tf32r(wout[k * 128 + n]));
    }
}

// ---------------------------------------------------------------------------
// Kernel 3: fused BN-normalize -> QKV (tf32 mma) -> attention -> out-proj
// smem floats: sy 6144 | qkv 3*5888 | small 512  => ~97 KB => 2 blocks/SM
// ---------------------------------------------------------------------------
#define QKV_BLK   184                       // per (item,head) block stride
#define SMEM_FLOATS (MT * 2048 + 3 * (NB * 8 * QKV_BLK) + 512)
#define SMEM_BYTES  (SMEM_FLOATS * 4)

__global__ void __launch_bounds__(256, 2)
main_kernel(const float* __restrict__ x,
            const float* __restrict__ b_out,
            const float* __restrict__ mask,
            float* __restrict__ out) {
    extern __shared__ float sm[];
    float* sy      = sm;                          // MT x 16 x 32 x 4 (A frags)
    float* qs      = sy + MT * 2048;              // 32 pair-blocks x 184
    float* kvk     = qs + NB * 8 * QKV_BLK;
    float* kvv     = kvk + NB * 8 * QKV_BLK;
    float* s_scale = kvv + NB * 8 * QKV_BLK;
    float* s_shift = s_scale + 128;
    float* s_mask  = s_shift + 128;
    float* s_bout  = s_mask + 128;

    const int tid  = threadIdx.x;
    const int lane = tid & 31;
    const int wrp  = tid >> 5;            // 0..7
    const int tig  = lane & 3;
    const int gid  = lane >> 2;
    const int row0 = blockIdx.x * ROWS;

    if (tid < 128) {
        s_scale[tid] = g_scale[tid];
        s_shift[tid] = g_shift[tid];
        s_bout [tid] = b_out[tid];
    }
    if (tid < 100) s_mask[tid] = mask[tid];
    __syncthreads();

    // ---- Phase 1: load + BN-normalize x into fragment-permuted sy ----------
    // rows 40..47 zero-filled (mma padding)
    {
        const float4* x4  = (const float4*)x;
        const float4* sc4 = (const float4*)s_scale;
        const float4* sh4 = (const float4*)s_shift;
        #pragma unroll
        for (int f = tid; f < MT * 16 * 32; f += 256) {
            int r = f >> 5, c4 = f & 31;
            float e0 = 0.f, e1 = 0.f, e2 = 0.f, e3 = 0.f;
            if (r < ROWS) {
                float4 v = x4[(size_t)(row0 + r) * 32 + c4];
                float4 sc = sc4[c4], sh = sh4[c4];
                e0 = fmaf(v.x, sc.x, sh.x);
                e1 = fmaf(v.y, sc.y, sh.y);
                e2 = fmaf(v.z, sc.z, sh.z);
                e3 = fmaf(v.w, sc.w, sh.w);
            }
            int m = r >> 4, rr = r & 15, ks = c4 >> 1, kx = ks & 7;
            int slot  = (rr >> 3) + 2 * (c4 & 1);
            int lane0 = (rr & 7) * 4;
            int base  = (m * 16 + ks) * 32;
            sy[(base + ((lane0 + 0) ^ kx)) * 4 + slot] = __uint_as_float(tf32r(e0));
            sy[(base + ((lane0 + 1) ^ kx)) * 4 + slot] = __uint_as_float(tf32r(e1));
            sy[(base + ((lane0 + 2) ^ kx)) * 4 + slot] = __uint_as_float(tf32r(e2));
            sy[(base + ((lane0 + 3) ^ kx)) * 4 + slot] = __uint_as_float(tf32r(e3));
        }
    }
    __syncthreads();

    // ---- Phase 2: QKV GEMM via tf32 mma. Warp w owns n-tiles 6w..6w+5,
    //      processed in 2 passes of 3 to cap register pressure.
    {
        const uint2* gb = (const uint2*)g_wqkv_perm;
        #pragma unroll
        for (int pass = 0; pass < 2; ++pass) {
            const int nt0 = 6 * wrp + 3 * pass;
            float acc[MT][3][4];
            #pragma unroll
            for (int m = 0; m < MT; ++m)
                #pragma unroll
                for (int n = 0; n < 3; ++n)
                    #pragma unroll
                    for (int e = 0; e < 4; ++e) acc[m][n][e] = 0.f;

            #pragma unroll 4
            for (int ks = 0; ks < 16; ++ks) {
                uint2 b[3];
                #pragma unroll
                for (int n = 0; n < 3; ++n)
                    b[n] = __ldg(&gb[((nt0 + n) * 16 + ks) * 32 + lane]);
                const int kx = ks & 7;
                #pragma unroll
                for (int m = 0; m < MT; ++m) {
                    float4 a = *(const float4*)&sy[((m * 16 + ks) * 32 + (lane ^ kx)) * 4];
                    unsigned a0 = __float_as_uint(a.x), a1 = __float_as_uint(a.y);
                    unsigned a2 = __float_as_uint(a.z), a3 = __float_as_uint(a.w);
                    #pragma unroll
                    for (int n = 0; n < 3; ++n)
                        mma_tf32(acc[m][n][0], acc[m][n][1], acc[m][n][2], acc[m][n][3],
                                 a0, a1, a2, a3, b[n].x, b[n].y);
                }
            }

            // scatter C into q/k/v blocked layout (skip pad rows >= 40)
            #pragma unroll
            for (int m = 0; m < MT; ++m)
                #pragma unroll
                for (int n = 0; n < 3; ++n) {
                    int nt = nt0 + n;
                    int Cn = nt * 8 + 2 * tig;
                    int sel = Cn >> 7;
                    int cc  = Cn & 127;
                    int h   = cc >> 4;
                    int dh  = cc & 15;
                    float* dst = (sel == 0) ? qs : (sel == 1) ? kvk : kvv;
                    int R0 = m * 16 + gid;
                    int li0 = R0 / 10, i0 = R0 - li0 * 10;
                    *(float2*)&dst[(li0 * 8 + h) * QKV_BLK + i0 * 16 + dh] =
                        make_float2(acc[m][n][0], acc[m][n][1]);
                    if (m < MT - 1) {
                        int R1 = R0 + 8;
                        int li1 = R1 / 10, i1 = R1 - li1 * 10;
                        *(float2*)&dst[(li1 * 8 + h) * QKV_BLK + i1 * 16 + dh] =
                            make_float2(acc[m][n][2], acc[m][n][3]);
                    }
                }
        }
    }
    __syncthreads();

    // ---- Phase 3: masked attention, row-split: 8 threads per (item,head) ---
    {
        const int pair = tid >> 3;          // 0..31 == li*8+h
        const int sub  = tid & 7;
        const float* qb = qs  + pair * QKV_BLK;
        const float* kb = kvk + pair * QKV_BLK;
        const float* vb = kvv + pair * QKV_BLK;

        #pragma unroll
        for (int rep = 0; rep < 2; ++rep) {
            const int i = rep == 0 ? sub : 8 + sub;
            if (i < 10) {
                float4 q0 = *(const float4*)&qb[i * 16 + 0];
                float4 q1 = *(const float4*)&qb[i * 16 + 4];
                float4 q2 = *(const float4*)&qb[i * 16 + 8];
                float4 q3 = *(const float4*)&qb[i * 16 + 12];

                float d[10], mx = -1e30f;
                #pragma unroll
                for (int j = 0; j < 10; ++j) {
                    float4 k0 = *(const float4*)&kb[j * 16 + 0];
                    float4 k1 = *(const float4*)&kb[j * 16 + 4];
                    float4 k2 = *(const float4*)&kb[j * 16 + 8];
                    float4 k3 = *(const float4*)&kb[j * 16 + 12];
                    float p = q0.x * k0.x + q0.y * k0.y + q0.z * k0.z + q0.w * k0.w;
                    p = fmaf(q1.x, k1.x, fmaf(q1.y, k1.y, fmaf(q1.z, k1.z, fmaf(q1.w, k1.w, p))));
                    p = fmaf(q2.x, k2.x, fmaf(q2.y, k2.y, fmaf(q2.z, k2.z, fmaf(q2.w, k2.w, p))));
                    p = fmaf(q3.x, k3.x, fmaf(q3.y, k3.y, fmaf(q3.z, k3.z, fmaf(q3.w, k3.w, p))));
                    p = p * 0.25f * s_mask[i * 10 + j];
                    d[j] = p;
                    mx = fmaxf(mx, p);
                }
                float ssum = 0.f;
                #pragma unroll
                for (int j = 0; j < 10; ++j) { d[j] = __expf(d[j] - mx); ssum += d[j]; }
                const float inv = 1.0f / ssum;

                float o[16];
                #pragma unroll
                for (int t = 0; t < 16; ++t) o[t] = 0.f;
                #pragma unroll
                for (int j = 0; j < 10; ++j) {
                    float a = d[j] * inv;
                    #pragma unroll
                    for (int t = 0; t < 4; ++t) {
                        float4 v = *(const float4*)&vb[j * 16 + t * 4];
                        o[t * 4 + 0] = fmaf(a, v.x, o[t * 4 + 0]);
                        o[t * 4 + 1] = fmaf(a, v.y, o[t * 4 + 1]);
                        o[t * 4 + 2] = fmaf(a, v.z, o[t * 4 + 2]);
                        o[t * 4 + 3] = fmaf(a, v.w, o[t * 4 + 3]);
                    }
                }
                // scatter into sy (fragment-permuted, XOR swizzle)
                const int li = pair >> 3;
                const int h  = pair & 7;
                int R = li * 10 + i;
                int m = R >> 4, rr = R & 15;
                int slotbase = (rr >> 3);
                int lane0 = (rr & 7) * 4;
                #pragma unroll
                for (int g4 = 0; g4 < 4; ++g4) {       // 4-float groups
                    int C0 = h * 16 + g4 * 4;
                    int ks = C0 >> 3, kx = ks & 7;
                    int slot = slotbase + 2 * (g4 & 1);
                    int base = (m * 16 + ks) * 32;
                    sy[(base + ((lane0 + 0) ^ kx)) * 4 + slot] = __uint_as_float(tf32r(o[g4 * 4 + 0]));
                    sy[(base + ((lane0 + 1) ^ kx)) * 4 + slot] = __uint_as_float(tf32r(o[g4 * 4 + 1]));
                    sy[(base + ((lane0 + 2) ^ kx)) * 4 + slot] = __uint_as_float(tf32r(o[g4 * 4 + 2]));
                    sy[(base + ((lane0 + 3) ^ kx)) * 4 + slot] = __uint_as_float(tf32r(o[g4 * 4 + 3]));
                }
            }
        }
    }
    __syncthreads();
    // NOTE: pad rows 40..47 of sy still hold zeros from phase 1 (attention never
    // writes them), so phase 4 mma padding stays clean.

    // ---- Phase 4: out projection via tf32 mma. Warp w owns n-tiles 2w,2w+1 -
    {
        float acc[MT][2][4];
        #pragma unroll
        for (int m = 0; m < MT; ++m)
            #pragma unroll
            for (int n = 0; n < 2; ++n)
                #pragma unroll
                for (int e = 0; e < 4; ++e) acc[m][n][e] = 0.f;

        const uint2* gb = (const uint2*)g_wout_perm;
        const int nt0 = 2 * wrp;

        #pragma unroll 4
        for (int ks = 0; ks < 16; ++ks) {
            uint2 b[2];
            #pragma unroll
            for (int n = 0; n < 2; ++n)
                b[n] = __ldg(&gb[((nt0 + n) * 16 + ks) * 32 + lane]);
            const int kx = ks & 7;
            #pragma unroll
            for (int m = 0; m < MT; ++m) {
                float4 a = *(const float4*)&sy[((m * 16 + ks) * 32 + (lane ^ kx)) * 4];
                unsigned a0 = __float_as_uint(a.x), a1 = __float_as_uint(a.y);
                unsigned a2 = __float_as_uint(a.z), a3 = __float_as_uint(a.w);
                #pragma unroll
                for (int n = 0; n < 2; ++n)
                    mma_tf32(acc[m][n][0], acc[m][n][1], acc[m][n][2], acc[m][n][3],
                             a0, a1, a2, a3, b[n].x, b[n].y);
            }
        }

        #pragma unroll
        for (int m = 0; m < MT; ++m)
            #pragma unroll
            for (int n = 0; n < 2; ++n) {
                int col = (nt0 + n) * 8 + 2 * tig;
                float b0 = s_bout[col], b1 = s_bout[col + 1];
                int R0 = m * 16 + gid;
                *(float2*)&out[(size_t)(row0 + R0) * 128 + col] =
                    make_float2(acc[m][n][0] + b0, acc[m][n][1] + b1);
                if (m < MT - 1) {
                    *(float2*)&out[(size_t)(row0 + R0 + 8) * 128 + col] =
                        make_float2(acc[m][n][2] + b0, acc[m][n][3] + b1);
                }
            }
    }
}

// ---------------------------------------------------------------------------
extern "C" void kernel_launch(void* const* d_in, const int* in_sizes, int n_in,
                              void* d_out, int out_size) {
    const float* x     = (const float*)d_in[0];
    const float* gamma = (const float*)d_in[1];
    const float* beta  = (const float*)d_in[2];
    const float* w_qkv = (const float*)d_in[3];
    const float* w_out = (const float*)d_in[4];
    const float* b_out = (const float*)d_in[5];
    const float* mask  = (const float*)d_in[6];
    float* out = (float*)d_out;

    cudaFuncSetAttribute(main_kernel,
                         cudaFuncAttributeMaxDynamicSharedMemorySize, SMEM_BYTES);

    stats_kernel<<<NBLK_STATS, 256>>>((const float4*)x);
    permute_weights<<<192, 256>>>(w_qkv, w_out);
    finalize_kernel<<<1, 1024>>>(gamma, beta);
    main_kernel<<<BTOT / NB, 256, SMEM_BYTES>>>(x, b_out, mask, out);
}

// round 4
// speedup vs baseline: 3.2711x; 1.1199x over previous
#include <cuda_runtime.h>

// ---------------------------------------------------------------------------
// Problem constants
#define R_TOTAL   327680          // N*T*VN rows
#define BTOT      32768           // N*T graph items
#define NB        4               // items per block in main kernel
#define ROWS      (NB*10)         // 40 rows per block -> 3 m-tiles (48, 8 pad)
#define MT        3               // m-tiles
#define NBLK_STATS 2048
#define BN_EPS    1e-5f

// Scratch (allocation-free)
__device__ float g_psum[NBLK_STATS * 128];
__device__ float g_psq [NBLK_STATS * 128];
__device__ float g_scale[128];
__device__ float g_shift[128];
// Pre-permuted weights in mma fragment order (tf32-rounded bits)
__device__ float g_wqkv_perm[48 * 16 * 32 * 2];
__device__ float g_wout_perm[16 * 16 * 32 * 2];

// ---------------------------------------------------------------------------
__device__ __forceinline__ unsigned tf32r(float f) {
    unsigned r;
    asm("cvt.rna.tf32.f32 %0, %1;" : "=r"(r) : "f"(f));
    return r;
}

__device__ __forceinline__ void mma_tf32(float& c0, float& c1, float& c2, float& c3,
                                         unsigned a0, unsigned a1, unsigned a2, unsigned a3,
                                         unsigned b0, unsigned b1) {
    asm volatile("mma.sync.aligned.m16n8k8.row.col.f32.tf32.tf32.f32 "
                 "{%0,%1,%2,%3}, {%4,%5,%6,%7}, {%8,%9}, {%0,%1,%2,%3};\n"
                 : "+f"(c0), "+f"(c1), "+f"(c2), "+f"(c3)
                 : "r"(a0), "r"(a1), "r"(a2), "r"(a3), "r"(b0), "r"(b1));
}

// ---------------------------------------------------------------------------
// Kernel 1: per-channel sum / sumsq partials (DRAM-bound, ~32us, near optimal)
// ---------------------------------------------------------------------------
__global__ void __launch_bounds__(256) stats_kernel(const float4* __restrict__ x4) {
    __shared__ float s_sum[256][4];
    __shared__ float s_sq [256][4];
    const int tid  = threadIdx.x;
    const int lane = tid & 31;
    const int slot = tid >> 5;

    float4 sum = make_float4(0.f, 0.f, 0.f, 0.f);
    float4 sq  = make_float4(0.f, 0.f, 0.f, 0.f);

    int row = blockIdx.x * 8 + slot;
    const int stride = NBLK_STATS * 8;
    #pragma unroll 4
    for (int it = 0; it < R_TOTAL / stride; ++it) {
        float4 v = x4[(size_t)row * 32 + lane];
        sum.x += v.x; sum.y += v.y; sum.z += v.z; sum.w += v.w;
        sq.x += v.x * v.x; sq.y += v.y * v.y; sq.z += v.z * v.z; sq.w += v.w * v.w;
        row += stride;
    }
    s_sum[tid][0] = sum.x; s_sum[tid][1] = sum.y; s_sum[tid][2] = sum.z; s_sum[tid][3] = sum.w;
    s_sq [tid][0] = sq.x;  s_sq [tid][1] = sq.y;  s_sq [tid][2] = sq.z;  s_sq [tid][3] = sq.w;
    __syncthreads();
    for (int off = 128; off >= 32; off >>= 1) {
        if (tid < off) {
            #pragma unroll
            for (int j = 0; j < 4; ++j) {
                s_sum[tid][j] += s_sum[tid + off][j];
                s_sq [tid][j] += s_sq [tid + off][j];
            }
        }
        __syncthreads();
    }
    if (tid < 32) {
        #pragma unroll
        for (int j = 0; j < 4; ++j) {
            g_psum[blockIdx.x * 128 + tid * 4 + j] = s_sum[tid][j];
            g_psq [blockIdx.x * 128 + tid * 4 + j] = s_sq [tid][j];
        }
    }
}

// ---------------------------------------------------------------------------
// Kernel 2: finalize BN affine params (parallel)
// ---------------------------------------------------------------------------
__global__ void __launch_bounds__(1024) finalize_kernel(const float* __restrict__ gamma,
                                                        const float* __restrict__ beta) {
    __shared__ float r_sum[1024];
    __shared__ float r_sq [1024];
    const int tid = threadIdx.x;
    const int c = tid & 127;
    const int s = tid >> 7;
    float sum = 0.f, sq = 0.f;
    #pragma unroll 8
    for (int b = s; b < NBLK_STATS; b += 8) {
        sum += g_psum[b * 128 + c];
        sq  += g_psq [b * 128 + c];
    }
    r_sum[tid] = sum;
    r_sq [tid] = sq;
    __syncthreads();
    if (tid < 128) {
        float S = 0.f, Q = 0.f;
        #pragma unroll
        for (int j = 0; j < 8; ++j) { S += r_sum[j * 128 + c]; Q += r_sq[j * 128 + c]; }
        const float inv_n = 1.0f / (float)R_TOTAL;
        float mean = S * inv_n;
        float var  = Q * inv_n - mean * mean;
        float sc   = gamma[c] * rsqrtf(var + BN_EPS);
        g_scale[c] = sc;
        g_shift[c] = beta[c] - mean * sc;
    }
}

// ---------------------------------------------------------------------------
// Kernel 2b: permute weights into mma B-fragment order (tf32 rounded)
// ---------------------------------------------------------------------------
__global__ void permute_weights(const float* __restrict__ wqkv,
                                const float* __restrict__ wout) {
    int idx = blockIdx.x * 256 + threadIdx.x;     // 49152 total
    {
        int t  = idx & 1;
        int l  = (idx >> 1) & 31;
        int ks = (idx >> 6) & 15;
        int nt = idx >> 10;
        int k = ks * 8 + (l & 3) + t * 4;
        int n = nt * 8 + (l >> 2);
        g_wqkv_perm[idx] = __uint_as_float(tf32r(wqkv[k * 384 + n]));
    }
    if (idx < 16384) {
        int t  = idx & 1;
        int l  = (idx >> 1) & 31;
        int ks = (idx >> 6) & 15;
        int nt = idx >> 10;
        int k = ks * 8 + (l & 3) + t * 4;
        int n = nt * 8 + (l >> 2);
        g_wout_perm[idx] = __uint_as_float(tf32r(wout[k * 128 + n]));
    }
}

// ---------------------------------------------------------------------------
// Kernel 3: fused BN-normalize -> QKV (tf32 mma) -> attention -> out-proj
// ---------------------------------------------------------------------------
#define QKV_BLK   184
#define SMEM_FLOATS (MT * 2048 + 3 * (NB * 8 * QKV_BLK) + 512)
#define SMEM_BYTES  (SMEM_FLOATS * 4)

__global__ void __launch_bounds__(256, 2)
main_kernel(const float* __restrict__ x,
            const float* __restrict__ b_out,
            const float* __restrict__ mask,
            float* __restrict__ out) {
    extern __shared__ float sm[];
    float* sy      = sm;                          // MT x 16 x 32 x 4 (A frags)
    float* qs      = sy + MT * 2048;
    float* kvk     = qs + NB * 8 * QKV_BLK;
    float* kvv     = kvk + NB * 8 * QKV_BLK;
    float* s_scale = kvv + NB * 8 * QKV_BLK;
    float* s_shift = s_scale + 128;
    float* s_mask  = s_shift + 128;
    float* s_bout  = s_mask + 128;

    const int tid  = threadIdx.x;
    const int lane = tid & 31;
    const int wrp  = tid >> 5;
    const int tig  = lane & 3;
    const int gid  = lane >> 2;
    const int row0 = blockIdx.x * ROWS;

    if (tid < 128) {
        s_scale[tid] = g_scale[tid];
        s_shift[tid] = g_shift[tid];
        s_bout [tid] = b_out[tid];
    }
    if (tid < 100) s_mask[tid] = mask[tid];
    __syncthreads();

    // ---- Phase 1: load + BN-normalize x into fragment-permuted sy ----------
    {
        const float4* x4  = (const float4*)x;
        const float4* sc4 = (const float4*)s_scale;
        const float4* sh4 = (const float4*)s_shift;
        #pragma unroll
        for (int f = tid; f < MT * 16 * 32; f += 256) {
            int r = f >> 5, c4 = f & 31;
            float e0 = 0.f, e1 = 0.f, e2 = 0.f, e3 = 0.f;
            if (r < ROWS) {
                float4 v = x4[(size_t)(row0 + r) * 32 + c4];
                float4 sc = sc4[c4], sh = sh4[c4];
                e0 = fmaf(v.x, sc.x, sh.x);
                e1 = fmaf(v.y, sc.y, sh.y);
                e2 = fmaf(v.z, sc.z, sh.z);
                e3 = fmaf(v.w, sc.w, sh.w);
            }
            int m = r >> 4, rr = r & 15, ks = c4 >> 1, kx = ks & 7;
            int slot  = (rr >> 3) + 2 * (c4 & 1);
            int lane0 = (rr & 7) * 4;
            float* dst = sy + (m * 16 + ks) * 128 + slot;   // *4 folded
            dst[((lane0 + 0) ^ kx) * 4] = __uint_as_float(tf32r(e0));
            dst[((lane0 + 1) ^ kx) * 4] = __uint_as_float(tf32r(e1));
            dst[((lane0 + 2) ^ kx) * 4] = __uint_as_float(tf32r(e2));
            dst[((lane0 + 3) ^ kx) * 4] = __uint_as_float(tf32r(e3));
        }
    }
    __syncthreads();

    // ---- Phase 2: QKV GEMM via tf32 mma, SINGLE pass, warp owns 6 n-tiles --
    {
        const uint2* gb = (const uint2*)g_wqkv_perm;
        const int nt0 = 6 * wrp;
        float acc[MT][6][4];
        #pragma unroll
        for (int m = 0; m < MT; ++m)
            #pragma unroll
            for (int n = 0; n < 6; ++n)
                #pragma unroll
                for (int e = 0; e < 4; ++e) acc[m][n][e] = 0.f;

        const uint2* gwp = gb + nt0 * 16 * 32 + lane;
        #pragma unroll 2
        for (int ks = 0; ks < 16; ++ks) {
            uint2 b[6];
            #pragma unroll
            for (int n = 0; n < 6; ++n)
                b[n] = __ldg(gwp + (n * 16 + ks) * 32);
            const int lx = lane ^ (ks & 7);
            #pragma unroll
            for (int m = 0; m < MT; ++m) {
                float4 a = *(const float4*)&sy[(m * 16 + ks) * 128 + lx * 4];
                unsigned a0 = __float_as_uint(a.x), a1 = __float_as_uint(a.y);
                unsigned a2 = __float_as_uint(a.z), a3 = __float_as_uint(a.w);
                #pragma unroll
                for (int n = 0; n < 6; ++n)
                    mma_tf32(acc[m][n][0], acc[m][n][1], acc[m][n][2], acc[m][n][3],
                             a0, a1, a2, a3, b[n].x, b[n].y);
            }
        }

        // scatter C into q/k/v blocked layout (skip pad rows >= 40)
        #pragma unroll
        for (int m = 0; m < MT; ++m) {
            int R0 = m * 16 + gid;
            int li0 = R0 / 10, i0 = R0 - li0 * 10;
            int R1 = R0 + 8;
            int li1 = R1 / 10, i1 = R1 - li1 * 10;
            int off0 = li0 * 8 * QKV_BLK + i0 * 16;
            int off1 = li1 * 8 * QKV_BLK + i1 * 16;
            #pragma unroll
            for (int n = 0; n < 6; ++n) {
                int Cn = (nt0 + n) * 8 + 2 * tig;
                int sel = Cn >> 7;
                int cc  = Cn & 127;
                int h   = cc >> 4;
                int dh  = cc & 15;
                float* dst = (sel == 0) ? qs : (sel == 1) ? kvk : kvv;
                *(float2*)&dst[off0 + h * QKV_BLK + dh] =
                    make_float2(acc[m][n][0], acc[m][n][1]);
                if (m < MT - 1)
                    *(float2*)&dst[off1 + h * QKV_BLK + dh] =
                        make_float2(acc[m][n][2], acc[m][n][3]);
            }
        }
    }
    __syncthreads();

    // ---- Phase 3: masked attention, 8 threads/(item,head); each thread does
    //      rows i0=sub and i1=sub+8 TOGETHER sharing the K/V loads.
    {
        const int pair = tid >> 3;          // 0..31 == li*8+h
        const int sub  = tid & 7;
        const int i0   = sub;
        const int i1   = sub + 8;
        const bool has2 = (sub < 2);        // i1 < 10
        const float* qb = qs  + pair * QKV_BLK;
        const float* kb = kvk + pair * QKV_BLK;
        const float* vb = kvv + pair * QKV_BLK;
        const int mrow1 = has2 ? i1 * 10 : 0;

        float4 qA0 = *(const float4*)&qb[i0 * 16 + 0];
        float4 qA1 = *(const float4*)&qb[i0 * 16 + 4];
        float4 qA2 = *(const float4*)&qb[i0 * 16 + 8];
        float4 qA3 = *(const float4*)&qb[i0 * 16 + 12];
        float4 qB0 = *(const float4*)&qb[i1 * 16 + 0];   // in-bounds (<QKV_BLK)
        float4 qB1 = *(const float4*)&qb[i1 * 16 + 4];
        float4 qB2 = *(const float4*)&qb[i1 * 16 + 8];
        float4 qB3 = *(const float4*)&qb[i1 * 16 + 12];

        float d0[10], d1[10];
        float mx0 = -1e30f, mx1 = -1e30f;
        #pragma unroll
        for (int j = 0; j < 10; ++j) {
            float4 k0 = *(const float4*)&kb[j * 16 + 0];
            float4 k1 = *(const float4*)&kb[j * 16 + 4];
            float4 k2 = *(const float4*)&kb[j * 16 + 8];
            float4 k3 = *(const float4*)&kb[j * 16 + 12];
            float p0 = qA0.x * k0.x + qA0.y * k0.y + qA0.z * k0.z + qA0.w * k0.w;
            p0 = fmaf(qA1.x, k1.x, fmaf(qA1.y, k1.y, fmaf(qA1.z, k1.z, fmaf(qA1.w, k1.w, p0))));
            p0 = fmaf(qA2.x, k2.x, fmaf(qA2.y, k2.y, fmaf(qA2.z, k2.z, fmaf(qA2.w, k2.w, p0))));
            p0 = fmaf(qA3.x, k3.x, fmaf(qA3.y, k3.y, fmaf(qA3.z, k3.z, fmaf(qA3.w, k3.w, p0))));
            float p1 = qB0.x * k0.x + qB0.y * k0.y + qB0.z * k0.z + qB0.w * k0.w;
            p1 = fmaf(qB1.x, k1.x, fmaf(qB1.y, k1.y, fmaf(qB1.z, k1.z, fmaf(qB1.w, k1.w, p1))));
            p1 = fmaf(qB2.x, k2.x, fmaf(qB2.y, k2.y, fmaf(qB2.z, k2.z, fmaf(qB2.w, k2.w, p1))));
            p1 = fmaf(qB3.x, k3.x, fmaf(qB3.y, k3.y, fmaf(qB3.z, k3.z, fmaf(qB3.w, k3.w, p1))));
            p0 = p0 * 0.25f * s_mask[i0 * 10 + j];
            p1 = p1 * 0.25f * s_mask[mrow1 + j];
            d0[j] = p0; mx0 = fmaxf(mx0, p0);
            d1[j] = p1; mx1 = fmaxf(mx1, p1);
        }
        float s0 = 0.f, s1 = 0.f;
        #pragma unroll
        for (int j = 0; j < 10; ++j) {
            d0[j] = __expf(d0[j] - mx0); s0 += d0[j];
            d1[j] = __expf(d1[j] - mx1); s1 += d1[j];
        }
        const float inv0 = 1.0f / s0;
        const float inv1 = 1.0f / s1;

        float o0[16], o1[16];
        #pragma unroll
        for (int t = 0; t < 16; ++t) { o0[t] = 0.f; o1[t] = 0.f; }
        #pragma unroll
        for (int j = 0; j < 10; ++j) {
            float a0 = d0[j] * inv0;
            float a1 = d1[j] * inv1;
            #pragma unroll
            for (int t = 0; t < 4; ++t) {
                float4 v = *(const float4*)&vb[j * 16 + t * 4];
                o0[t * 4 + 0] = fmaf(a0, v.x, o0[t * 4 + 0]);
                o0[t * 4 + 1] = fmaf(a0, v.y, o0[t * 4 + 1]);
                o0[t * 4 + 2] = fmaf(a0, v.z, o0[t * 4 + 2]);
                o0[t * 4 + 3] = fmaf(a0, v.w, o0[t * 4 + 3]);
                o1[t * 4 + 0] = fmaf(a1, v.x, o1[t * 4 + 0]);
                o1[t * 4 + 1] = fmaf(a1, v.y, o1[t * 4 + 1]);
                o1[t * 4 + 2] = fmaf(a1, v.z, o1[t * 4 + 2]);
                o1[t * 4 + 3] = fmaf(a1, v.w, o1[t * 4 + 3]);
            }
        }

        // scatter into sy (fragment-permuted, XOR swizzle)
        const int li = pair >> 3;
        const int h  = pair & 7;
        #pragma unroll
        for (int rep = 0; rep < 2; ++rep) {
            if (rep == 1 && !has2) break;
            const float* o = rep == 0 ? o0 : o1;
            int R = li * 10 + (rep == 0 ? i0 : i1);
            int m = R >> 4, rr = R & 15;
            int slotbase = (rr >> 3);
            int lane0 = (rr & 7) * 4;
            #pragma unroll
            for (int g4 = 0; g4 < 4; ++g4) {
                int C0 = h * 16 + g4 * 4;
                int ks = C0 >> 3, kx = ks & 7;
                int slot = slotbase + 2 * (g4 & 1);
                float* dst = sy + (m * 16 + ks) * 128 + slot;
                dst[((lane0 + 0) ^ kx) * 4] = __uint_as_float(tf32r(o[g4 * 4 + 0]));
                dst[((lane0 + 1) ^ kx) * 4] = __uint_as_float(tf32r(o[g4 * 4 + 1]));
                dst[((lane0 + 2) ^ kx) * 4] = __uint_as_float(tf32r(o[g4 * 4 + 2]));
                dst[((lane0 + 3) ^ kx) * 4] = __uint_as_float(tf32r(o[g4 * 4 + 3]));
            }
        }
    }
    __syncthreads();
    // pad rows 40..47 of sy still hold zeros from phase 1.

    // ---- Phase 4: out projection via tf32 mma. Warp w owns n-tiles 2w,2w+1 -
    {
        float acc[MT][2][4];
        #pragma unroll
        for (int m = 0; m < MT; ++m)
            #pragma unroll
            for (int n = 0; n < 2; ++n)
                #pragma unroll
                for (int e = 0; e < 4; ++e) acc[m][n][e] = 0.f;

        const uint2* gb = (const uint2*)g_wout_perm;
        const int nt0 = 2 * wrp;
        const uint2* gwp = gb + nt0 * 16 * 32 + lane;

        #pragma unroll 4
        for (int ks = 0; ks < 16; ++ks) {
            uint2 b[2];
            #pragma unroll
            for (int n = 0; n < 2; ++n)
                b[n] = __ldg(gwp + (n * 16 + ks) * 32);
            const int lx = lane ^ (ks & 7);
            #pragma unroll
            for (int m = 0; m < MT; ++m) {
                float4 a = *(const float4*)&sy[(m * 16 + ks) * 128 + lx * 4];
                unsigned a0 = __float_as_uint(a.x), a1 = __float_as_uint(a.y);
                unsigned a2 = __float_as_uint(a.z), a3 = __float_as_uint(a.w);
                #pragma unroll
                for (int n = 0; n < 2; ++n)
                    mma_tf32(acc[m][n][0], acc[m][n][1], acc[m][n][2], acc[m][n][3],
                             a0, a1, a2, a3, b[n].x, b[n].y);
            }
        }

        #pragma unroll
        for (int m = 0; m < MT; ++m)
            #pragma unroll
            for (int n = 0; n < 2; ++n) {
                int col = (nt0 + n) * 8 + 2 * tig;
                float b0 = s_bout[col], b1 = s_bout[col + 1];
                int R0 = m * 16 + gid;
                *(float2*)&out[(size_t)(row0 + R0) * 128 + col] =
                    make_float2(acc[m][n][0] + b0, acc[m][n][1] + b1);
                if (m < MT - 1) {
                    *(float2*)&out[(size_t)(row0 + R0 + 8) * 128 + col] =
                        make_float2(acc[m][n][2] + b0, acc[m][n][3] + b1);
                }
            }
    }
}

// ---------------------------------------------------------------------------
extern "C" void kernel_launch(void* const* d_in, const int* in_sizes, int n_in,
                              void* d_out, int out_size) {
    const float* x     = (const float*)d_in[0];
    const float* gamma = (const float*)d_in[1];
    const float* beta  = (const float*)d_in[2];
    const float* w_qkv = (const float*)d_in[3];
    const float* w_out = (const float*)d_in[4];
    const float* b_out = (const float*)d_in[5];
    const float* mask  = (const float*)d_in[6];
    float* out = (float*)d_out;

    cudaFuncSetAttribute(main_kernel,
                         cudaFuncAttributeMaxDynamicSharedMemorySize, SMEM_BYTES);

    stats_kernel<<<NBLK_STATS, 256>>>((const float4*)x);
    permute_weights<<<192, 256>>>(w_qkv, w_out);
    finalize_kernel<<<1, 1024>>>(gamma, beta);
    main_kernel<<<BTOT / NB, 256, SMEM_BYTES>>>(x, b_out, mask, out);
}

// round 5
// speedup vs baseline: 4.3835x; 1.3401x over previous
#include <cuda_runtime.h>
#include <cuda_fp16.h>

// ---------------------------------------------------------------------------
// Problem constants
#define R_TOTAL   327680          // N*T*VN rows
#define BTOT      32768           // N*T graph items
#define NB        4               // items per block in main kernel
#define ROWS      (NB*10)         // 40 rows per block -> 3 m-tiles (48, 8 pad)
#define MT        3               // m-tiles
#define NBLK_STATS 2048
#define BN_EPS    1e-5f

// Scratch (allocation-free)
__device__ float g_psum[NBLK_STATS * 128];
__device__ float g_psq [NBLK_STATS * 128];
__device__ float g_scale[128];
__device__ float g_shift[128];
// Pre-permuted fp16 weights in m16n8k16 B-fragment order:
// [nt][kst(8)][lane(32)] -> uint2 {b0 = W[k0,k0+1][n], b1 = W[k0+8,k0+9][n]}
__device__ uint2 g_wqkv16[48 * 8 * 32];
__device__ uint2 g_wout16[16 * 8 * 32];

// ---------------------------------------------------------------------------
__device__ __forceinline__ unsigned pkh2(float a, float b) {
    __half2 h = __floats2half2_rn(a, b);     // .x = a (low) = even k
    return *(unsigned*)&h;
}

__device__ __forceinline__ void mma_f16(float& c0, float& c1, float& c2, float& c3,
                                        unsigned a0, unsigned a1, unsigned a2, unsigned a3,
                                        unsigned b0, unsigned b1) {
    asm volatile("mma.sync.aligned.m16n8k16.row.col.f32.f16.f16.f32 "
                 "{%0,%1,%2,%3}, {%4,%5,%6,%7}, {%8,%9}, {%0,%1,%2,%3};\n"
                 : "+f"(c0), "+f"(c1), "+f"(c2), "+f"(c3)
                 : "r"(a0), "r"(a1), "r"(a2), "r"(a3), "r"(b0), "r"(b1));
}

// ---------------------------------------------------------------------------
// Kernel 1: per-channel sum / sumsq partials (DRAM-bound, ~32us)
// ---------------------------------------------------------------------------
__global__ void __launch_bounds__(256) stats_kernel(const float4* __restrict__ x4) {
    __shared__ float s_sum[256][4];
    __shared__ float s_sq [256][4];
    const int tid  = threadIdx.x;
    const int lane = tid & 31;
    const int slot = tid >> 5;

    float4 sum = make_float4(0.f, 0.f, 0.f, 0.f);
    float4 sq  = make_float4(0.f, 0.f, 0.f, 0.f);

    int row = blockIdx.x * 8 + slot;
    const int stride = NBLK_STATS * 8;
    #pragma unroll 4
    for (int it = 0; it < R_TOTAL / stride; ++it) {
        float4 v = x4[(size_t)row * 32 + lane];
        sum.x += v.x; sum.y += v.y; sum.z += v.z; sum.w += v.w;
        sq.x += v.x * v.x; sq.y += v.y * v.y; sq.z += v.z * v.z; sq.w += v.w * v.w;
        row += stride;
    }
    s_sum[tid][0] = sum.x; s_sum[tid][1] = sum.y; s_sum[tid][2] = sum.z; s_sum[tid][3] = sum.w;
    s_sq [tid][0] = sq.x;  s_sq [tid][1] = sq.y;  s_sq [tid][2] = sq.z;  s_sq [tid][3] = sq.w;
    __syncthreads();
    for (int off = 128; off >= 32; off >>= 1) {
        if (tid < off) {
            #pragma unroll
            for (int j = 0; j < 4; ++j) {
                s_sum[tid][j] += s_sum[tid + off][j];
                s_sq [tid][j] += s_sq [tid + off][j];
            }
        }
        __syncthreads();
    }
    if (tid < 32) {
        #pragma unroll
        for (int j = 0; j < 4; ++j) {
            g_psum[blockIdx.x * 128 + tid * 4 + j] = s_sum[tid][j];
            g_psq [blockIdx.x * 128 + tid * 4 + j] = s_sq [tid][j];
        }
    }
}

// ---------------------------------------------------------------------------
// Kernel 2: finalize BN affine params (parallel)
// ---------------------------------------------------------------------------
__global__ void __launch_bounds__(1024) finalize_kernel(const float* __restrict__ gamma,
                                                        const float* __restrict__ beta) {
    __shared__ float r_sum[1024];
    __shared__ float r_sq [1024];
    const int tid = threadIdx.x;
    const int c = tid & 127;
    const int s = tid >> 7;
    float sum = 0.f, sq = 0.f;
    #pragma unroll 8
    for (int b = s; b < NBLK_STATS; b += 8) {
        sum += g_psum[b * 128 + c];
        sq  += g_psq [b * 128 + c];
    }
    r_sum[tid] = sum;
    r_sq [tid] = sq;
    __syncthreads();
    if (tid < 128) {
        float S = 0.f, Q = 0.f;
        #pragma unroll
        for (int j = 0; j < 8; ++j) { S += r_sum[j * 128 + c]; Q += r_sq[j * 128 + c]; }
        const float inv_n = 1.0f / (float)R_TOTAL;
        float mean = S * inv_n;
        float var  = Q * inv_n - mean * mean;
        float sc   = gamma[c] * rsqrtf(var + BN_EPS);
        g_scale[c] = sc;
        g_shift[c] = beta[c] - mean * sc;
    }
}

// ---------------------------------------------------------------------------
// Kernel 2b: permute weights into fp16 m16n8k16 B-fragment order
// ---------------------------------------------------------------------------
__global__ void permute_weights(const float* __restrict__ wqkv,
                                const float* __restrict__ wout) {
    int idx = blockIdx.x * 256 + threadIdx.x;     // 12288 total
    {
        int lane = idx & 31;
        int kst  = (idx >> 5) & 7;
        int nt   = idx >> 8;                      // 0..47
        int tig = lane & 3, gid = lane >> 2;
        int k0 = kst * 16 + 2 * tig;
        int n  = nt * 8 + gid;
        uint2 v;
        v.x = pkh2(wqkv[k0 * 384 + n],       wqkv[(k0 + 1) * 384 + n]);
        v.y = pkh2(wqkv[(k0 + 8) * 384 + n], wqkv[(k0 + 9) * 384 + n]);
        g_wqkv16[idx] = v;
    }
    if (idx < 16 * 8 * 32) {
        int lane = idx & 31;
        int kst  = (idx >> 5) & 7;
        int nt   = idx >> 8;                      // 0..15
        int tig = lane & 3, gid = lane >> 2;
        int k0 = kst * 16 + 2 * tig;
        int n  = nt * 8 + gid;
        uint2 v;
        v.x = pkh2(wout[k0 * 128 + n],       wout[(k0 + 1) * 128 + n]);
        v.y = pkh2(wout[(k0 + 8) * 128 + n], wout[(k0 + 9) * 128 + n]);
        g_wout16[idx] = v;
    }
}

// ---------------------------------------------------------------------------
// Kernel 3: fused BN-normalize -> QKV (fp16 mma) -> attention -> out-proj
// smem: sy16 3072 u32 (fp16 A-frags) | qkv fp32 3*5888 | small 512  ~85KB
// ---------------------------------------------------------------------------
#define QKV_BLK   184
#define SY_U32    (MT * 8 * 128)                  // 3072
#define SMEM_FLOATS (SY_U32 + 3 * (NB * 8 * QKV_BLK) + 512)
#define SMEM_BYTES  (SMEM_FLOATS * 4)

__global__ void __launch_bounds__(256, 2)
main_kernel(const float* __restrict__ x,
            const float* __restrict__ b_out,
            const float* __restrict__ mask,
            float* __restrict__ out) {
    extern __shared__ float sm[];
    unsigned* sy16 = (unsigned*)sm;               // [mt][kst][lane^kst][4 regs]
    float* qs      = sm + SY_U32;
    float* kvk     = qs + NB * 8 * QKV_BLK;
    float* kvv     = kvk + NB * 8 * QKV_BLK;
    float* s_scale = kvv + NB * 8 * QKV_BLK;
    float* s_shift = s_scale + 128;
    float* s_mask  = s_shift + 128;
    float* s_bout  = s_mask + 128;

    const int tid  = threadIdx.x;
    const int lane = tid & 31;
    const int wrp  = tid >> 5;
    const int tig  = lane & 3;
    const int gid  = lane >> 2;
    const int row0 = blockIdx.x * ROWS;

    if (tid < 128) {
        s_scale[tid] = g_scale[tid];
        s_shift[tid] = g_shift[tid];
        s_bout [tid] = b_out[tid];
    }
    if (tid < 100) s_mask[tid] = mask[tid];
    __syncthreads();

    // ---- Phase 1: load + BN-normalize x into fp16 A-fragment sy ------------
    // rows 40..47 zero (mma padding). Each (r,c4) covers channels 4c4..4c4+3:
    // tile (m, kst=c4>>2), tigs {t,t+1}, reg ri = rbit + (kc>=8?2:0)
    {
        const float4* x4  = (const float4*)x;
        const float4* sc4 = (const float4*)s_scale;
        const float4* sh4 = (const float4*)s_shift;
        #pragma unroll
        for (int f = tid; f < MT * 16 * 32; f += 256) {
            int r = f >> 5, c4 = f & 31;
            float e0 = 0.f, e1 = 0.f, e2 = 0.f, e3 = 0.f;
            if (r < ROWS) {
                float4 v = x4[(size_t)(row0 + r) * 32 + c4];
                float4 sc = sc4[c4], sh = sh4[c4];
                e0 = fmaf(v.x, sc.x, sh.x);
                e1 = fmaf(v.y, sc.y, sh.y);
                e2 = fmaf(v.z, sc.z, sh.z);
                e3 = fmaf(v.w, sc.w, sh.w);
            }
            int m = r >> 4, rr = r & 15;
            int g = rr & 7, rbit = rr >> 3;
            int kst = c4 >> 2;
            int kc  = 4 * (c4 & 3);
            int t   = (kc & 7) >> 1;                 // 0 or 2
            int ri  = rbit + (kc >= 8 ? 2 : 0);
            unsigned* base = sy16 + (m * 8 + kst) * 128;
            base[((g * 4 + t)     ^ kst) * 4 + ri] = pkh2(e0, e1);
            base[((g * 4 + t + 1) ^ kst) * 4 + ri] = pkh2(e2, e3);
        }
    }
    __syncthreads();

    // ---- Phase 2: QKV GEMM via fp16 mma (8 k-steps). Warp owns 6 n-tiles ---
    {
        const int nt0 = 6 * wrp;
        float acc[MT][6][4];
        #pragma unroll
        for (int m = 0; m < MT; ++m)
            #pragma unroll
            for (int n = 0; n < 6; ++n)
                #pragma unroll
                for (int e = 0; e < 4; ++e) acc[m][n][e] = 0.f;

        const uint2* gwp = g_wqkv16 + nt0 * 8 * 32 + lane;
        #pragma unroll 2
        for (int kst = 0; kst < 8; ++kst) {
            uint2 b[6];
            #pragma unroll
            for (int n = 0; n < 6; ++n)
                b[n] = __ldg(gwp + (n * 8 + kst) * 32);
            const int lx = lane ^ kst;
            #pragma unroll
            for (int m = 0; m < MT; ++m) {
                uint4 a = *(const uint4*)&sy16[(m * 8 + kst) * 128 + lx * 4];
                #pragma unroll
                for (int n = 0; n < 6; ++n)
                    mma_f16(acc[m][n][0], acc[m][n][1], acc[m][n][2], acc[m][n][3],
                            a.x, a.y, a.z, a.w, b[n].x, b[n].y);
            }
        }

        // scatter C into q/k/v blocked fp32 layout (skip pad rows >= 40)
        #pragma unroll
        for (int m = 0; m < MT; ++m) {
            int R0 = m * 16 + gid;
            int li0 = R0 / 10, i0 = R0 - li0 * 10;
            int R1 = R0 + 8;
            int li1 = R1 / 10, i1 = R1 - li1 * 10;
            int off0 = li0 * 8 * QKV_BLK + i0 * 16;
            int off1 = li1 * 8 * QKV_BLK + i1 * 16;
            #pragma unroll
            for (int n = 0; n < 6; ++n) {
                int Cn = (nt0 + n) * 8 + 2 * tig;
                int sel = Cn >> 7;
                int cc  = Cn & 127;
                int h   = cc >> 4;
                int dh  = cc & 15;
                float* dst = (sel == 0) ? qs : (sel == 1) ? kvk : kvv;
                *(float2*)&dst[off0 + h * QKV_BLK + dh] =
                    make_float2(acc[m][n][0], acc[m][n][1]);
                if (m < MT - 1)
                    *(float2*)&dst[off1 + h * QKV_BLK + dh] =
                        make_float2(acc[m][n][2], acc[m][n][3]);
            }
        }
    }
    __syncthreads();

    // ---- Phase 3: masked attention, 8 threads/(item,head); rows sub, sub+8
    //      share the K/V loads. Output scattered as fp16 A-fragments into sy.
    {
        const int pair = tid >> 3;          // 0..31 == li*8+h
        const int sub  = tid & 7;
        const int i0   = sub;
        const int i1   = sub + 8;
        const bool has2 = (sub < 2);        // i1 < 10
        const float* qb = qs  + pair * QKV_BLK;
        const float* kb = kvk + pair * QKV_BLK;
        const float* vb = kvv + pair * QKV_BLK;
        const int mrow1 = has2 ? i1 * 10 : 0;

        float4 qA0 = *(const float4*)&qb[i0 * 16 + 0];
        float4 qA1 = *(const float4*)&qb[i0 * 16 + 4];
        float4 qA2 = *(const float4*)&qb[i0 * 16 + 8];
        float4 qA3 = *(const float4*)&qb[i0 * 16 + 12];
        float4 qB0 = *(const float4*)&qb[i1 * 16 + 0];
        float4 qB1 = *(const float4*)&qb[i1 * 16 + 4];
        float4 qB2 = *(const float4*)&qb[i1 * 16 + 8];
        float4 qB3 = *(const float4*)&qb[i1 * 16 + 12];

        float d0[10], d1[10];
        float mx0 = -1e30f, mx1 = -1e30f;
        #pragma unroll
        for (int j = 0; j < 10; ++j) {
            float4 k0 = *(const float4*)&kb[j * 16 + 0];
            float4 k1 = *(const float4*)&kb[j * 16 + 4];
            float4 k2 = *(const float4*)&kb[j * 16 + 8];
            float4 k3 = *(const float4*)&kb[j * 16 + 12];
            float p0 = qA0.x * k0.x + qA0.y * k0.y + qA0.z * k0.z + qA0.w * k0.w;
            p0 = fmaf(qA1.x, k1.x, fmaf(qA1.y, k1.y, fmaf(qA1.z, k1.z, fmaf(qA1.w, k1.w, p0))));
            p0 = fmaf(qA2.x, k2.x, fmaf(qA2.y, k2.y, fmaf(qA2.z, k2.z, fmaf(qA2.w, k2.w, p0))));
            p0 = fmaf(qA3.x, k3.x, fmaf(qA3.y, k3.y, fmaf(qA3.z, k3.z, fmaf(qA3.w, k3.w, p0))));
            float p1 = qB0.x * k0.x + qB0.y * k0.y + qB0.z * k0.z + qB0.w * k0.w;
            p1 = fmaf(qB1.x, k1.x, fmaf(qB1.y, k1.y, fmaf(qB1.z, k1.z, fmaf(qB1.w, k1.w, p1))));
            p1 = fmaf(qB2.x, k2.x, fmaf(qB2.y, k2.y, fmaf(qB2.z, k2.z, fmaf(qB2.w, k2.w, p1))));
            p1 = fmaf(qB3.x, k3.x, fmaf(qB3.y, k3.y, fmaf(qB3.z, k3.z, fmaf(qB3.w, k3.w, p1))));
            p0 = p0 * 0.25f * s_mask[i0 * 10 + j];
            p1 = p1 * 0.25f * s_mask[mrow1 + j];
            d0[j] = p0; mx0 = fmaxf(mx0, p0);
            d1[j] = p1; mx1 = fmaxf(mx1, p1);
        }
        float s0 = 0.f, s1 = 0.f;
        #pragma unroll
        for (int j = 0; j < 10; ++j) {
            d0[j] = __expf(d0[j] - mx0); s0 += d0[j];
            d1[j] = __expf(d1[j] - mx1); s1 += d1[j];
        }
        const float inv0 = 1.0f / s0;
        const float inv1 = 1.0f / s1;

        float o0[16], o1[16];
        #pragma unroll
        for (int t = 0; t < 16; ++t) { o0[t] = 0.f; o1[t] = 0.f; }
        #pragma unroll
        for (int j = 0; j < 10; ++j) {
            float a0 = d0[j] * inv0;
            float a1 = d1[j] * inv1;
            #pragma unroll
            for (int t = 0; t < 4; ++t) {
                float4 v = *(const float4*)&vb[j * 16 + t * 4];
                o0[t * 4 + 0] = fmaf(a0, v.x, o0[t * 4 + 0]);
                o0[t * 4 + 1] = fmaf(a0, v.y, o0[t * 4 + 1]);
                o0[t * 4 + 2] = fmaf(a0, v.z, o0[t * 4 + 2]);
                o0[t * 4 + 3] = fmaf(a0, v.w, o0[t * 4 + 3]);
                o1[t * 4 + 0] = fmaf(a1, v.x, o1[t * 4 + 0]);
                o1[t * 4 + 1] = fmaf(a1, v.y, o1[t * 4 + 1]);
                o1[t * 4 + 2] = fmaf(a1, v.z, o1[t * 4 + 2]);
                o1[t * 4 + 3] = fmaf(a1, v.w, o1[t * 4 + 3]);
            }
        }

        // scatter rows as fp16 fragments: channels h*16+c -> tile (m, kst=h)
        const int li = pair >> 3;
        const int h  = pair & 7;
        #pragma unroll
        for (int rep = 0; rep < 2; ++rep) {
            if (rep == 1 && !has2) break;
            const float* o = rep == 0 ? o0 : o1;
            int R = li * 10 + (rep == 0 ? i0 : i1);
            int m = R >> 4, rr = R & 15;
            int g = rr & 7, rbit = rr >> 3;
            unsigned* base = sy16 + (m * 8 + h) * 128;
            #pragma unroll
            for (int t = 0; t < 4; ++t) {
                int ln = ((g * 4 + t) ^ h) * 4;
                base[ln + rbit]     = pkh2(o[2 * t],     o[2 * t + 1]);
                base[ln + rbit + 2] = pkh2(o[2 * t + 8], o[2 * t + 9]);
            }
        }
    }
    __syncthreads();
    // pad rows 40..47 of sy16 still hold zeros from phase 1.

    // ---- Phase 4: out projection via fp16 mma. Warp w owns n-tiles 2w,2w+1 -
    {
        float acc[MT][2][4];
        #pragma unroll
        for (int m = 0; m < MT; ++m)
            #pragma unroll
            for (int n = 0; n < 2; ++n)
                #pragma unroll
                for (int e = 0; e < 4; ++e) acc[m][n][e] = 0.f;

        const int nt0 = 2 * wrp;
        const uint2* gwp = g_wout16 + nt0 * 8 * 32 + lane;

        #pragma unroll 4
        for (int kst = 0; kst < 8; ++kst) {
            uint2 b[2];
            #pragma unroll
            for (int n = 0; n < 2; ++n)
                b[n] = __ldg(gwp + (n * 8 + kst) * 32);
            const int lx = lane ^ kst;
            #pragma unroll
            for (int m = 0; m < MT; ++m) {
                uint4 a = *(const uint4*)&sy16[(m * 8 + kst) * 128 + lx * 4];
                #pragma unroll
                for (int n = 0; n < 2; ++n)
                    mma_f16(acc[m][n][0], acc[m][n][1], acc[m][n][2], acc[m][n][3],
                            a.x, a.y, a.z, a.w, b[n].x, b[n].y);
            }
        }

        #pragma unroll
        for (int m = 0; m < MT; ++m)
            #pragma unroll
            for (int n = 0; n < 2; ++n) {
                int col = (nt0 + n) * 8 + 2 * tig;
                float b0 = s_bout[col], b1 = s_bout[col + 1];
                int R0 = m * 16 + gid;
                *(float2*)&out[(size_t)(row0 + R0) * 128 + col] =
                    make_float2(acc[m][n][0] + b0, acc[m][n][1] + b1);
                if (m < MT - 1) {
                    *(float2*)&out[(size_t)(row0 + R0 + 8) * 128 + col] =
                        make_float2(acc[m][n][2] + b0, acc[m][n][3] + b1);
                }
            }
    }
}

// ---------------------------------------------------------------------------
extern "C" void kernel_launch(void* const* d_in, const int* in_sizes, int n_in,
                              void* d_out, int out_size) {
    const float* x     = (const float*)d_in[0];
    const float* gamma = (const float*)d_in[1];
    const float* beta  = (const float*)d_in[2];
    const float* w_qkv = (const float*)d_in[3];
    const float* w_out = (const float*)d_in[4];
    const float* b_out = (const float*)d_in[5];
    const float* mask  = (const float*)d_in[6];
    float* out = (float*)d_out;

    cudaFuncSetAttribute(main_kernel,
                         cudaFuncAttributeMaxDynamicSharedMemorySize, SMEM_BYTES);

    stats_kernel<<<NBLK_STATS, 256>>>((const float4*)x);
    permute_weights<<<48, 256>>>(w_qkv, w_out);
    finalize_kernel<<<1, 1024>>>(gamma, beta);
    main_kernel<<<BTOT / NB, 256, SMEM_BYTES>>>(x, b_out, mask, out);
}

// round 6
// speedup vs baseline: 5.3672x; 1.2244x over previous
#include <cuda_runtime.h>
#include <cuda_fp16.h>

// ---------------------------------------------------------------------------
// Problem constants
#define R_TOTAL   327680          // N*T*VN rows
#define BTOT      32768           // N*T graph items
#define NB        8               // items per block
#define ROWS      (NB*10)         // 80 rows per block = 5 m-tiles, NO padding
#define MT        5               // m-tiles
#define NBLK_STATS 2048
#define BN_EPS    1e-5f

// Scratch (allocation-free)
__device__ float g_psum[NBLK_STATS * 128];
__device__ float g_psq [NBLK_STATS * 128];
__device__ float g_scale[128];
__device__ float g_shift[128];
// Pre-permuted fp16 weights in m16n8k16 B-fragment order:
// [nt][kst(8)][lane(32)] -> uint2 {b0 = W[k0,k0+1][n], b1 = W[k0+8,k0+9][n]}
__device__ uint2 g_wqkv16[48 * 8 * 32];
__device__ uint2 g_wout16[16 * 8 * 32];

// ---------------------------------------------------------------------------
__device__ __forceinline__ unsigned pkh2(float a, float b) {
    __half2 h = __floats2half2_rn(a, b);
    return *(unsigned*)&h;
}
__device__ __forceinline__ __half2 u2h2(unsigned u) { return *(__half2*)&u; }

__device__ __forceinline__ void mma_f16(float& c0, float& c1, float& c2, float& c3,
                                        unsigned a0, unsigned a1, unsigned a2, unsigned a3,
                                        unsigned b0, unsigned b1) {
    asm volatile("mma.sync.aligned.m16n8k16.row.col.f32.f16.f16.f32 "
                 "{%0,%1,%2,%3}, {%4,%5,%6,%7}, {%8,%9}, {%0,%1,%2,%3};\n"
                 : "+f"(c0), "+f"(c1), "+f"(c2), "+f"(c3)
                 : "r"(a0), "r"(a1), "r"(a2), "r"(a3), "r"(b0), "r"(b1));
}

// half2 dot of 16 fp16 values (2x uint4), fp32 finish
__device__ __forceinline__ float hdot16(uint4 qa, uint4 qb, uint4 ka, uint4 kb) {
    __half2 s = __hmul2(u2h2(qa.x), u2h2(ka.x));
    s = __hfma2(u2h2(qa.y), u2h2(ka.y), s);
    s = __hfma2(u2h2(qa.z), u2h2(ka.z), s);
    s = __hfma2(u2h2(qa.w), u2h2(ka.w), s);
    s = __hfma2(u2h2(qb.x), u2h2(kb.x), s);
    s = __hfma2(u2h2(qb.y), u2h2(kb.y), s);
    s = __hfma2(u2h2(qb.z), u2h2(kb.z), s);
    s = __hfma2(u2h2(qb.w), u2h2(kb.w), s);
    float2 f = __half22float2(s);
    return f.x + f.y;
}

// ---------------------------------------------------------------------------
// Kernel 1: per-channel sum / sumsq partials (DRAM-bound, ~32us)
// ---------------------------------------------------------------------------
__global__ void __launch_bounds__(256) stats_kernel(const float4* __restrict__ x4) {
    __shared__ float s_sum[256][4];
    __shared__ float s_sq [256][4];
    const int tid  = threadIdx.x;
    const int lane = tid & 31;
    const int slot = tid >> 5;

    float4 sum = make_float4(0.f, 0.f, 0.f, 0.f);
    float4 sq  = make_float4(0.f, 0.f, 0.f, 0.f);

    int row = blockIdx.x * 8 + slot;
    const int stride = NBLK_STATS * 8;
    #pragma unroll 4
    for (int it = 0; it < R_TOTAL / stride; ++it) {
        float4 v = x4[(size_t)row * 32 + lane];
        sum.x += v.x; sum.y += v.y; sum.z += v.z; sum.w += v.w;
        sq.x += v.x * v.x; sq.y += v.y * v.y; sq.z += v.z * v.z; sq.w += v.w * v.w;
        row += stride;
    }
    s_sum[tid][0] = sum.x; s_sum[tid][1] = sum.y; s_sum[tid][2] = sum.z; s_sum[tid][3] = sum.w;
    s_sq [tid][0] = sq.x;  s_sq [tid][1] = sq.y;  s_sq [tid][2] = sq.z;  s_sq [tid][3] = sq.w;
    __syncthreads();
    for (int off = 128; off >= 32; off >>= 1) {
        if (tid < off) {
            #pragma unroll
            for (int j = 0; j < 4; ++j) {
                s_sum[tid][j] += s_sum[tid + off][j];
                s_sq [tid][j] += s_sq [tid + off][j];
            }
        }
        __syncthreads();
    }
    if (tid < 32) {
        #pragma unroll
        for (int j = 0; j < 4; ++j) {
            g_psum[blockIdx.x * 128 + tid * 4 + j] = s_sum[tid][j];
            g_psq [blockIdx.x * 128 + tid * 4 + j] = s_sq [tid][j];
        }
    }
}

// ---------------------------------------------------------------------------
// Kernel 2: finalize BN affine params (parallel)
// ---------------------------------------------------------------------------
__global__ void __launch_bounds__(1024) finalize_kernel(const float* __restrict__ gamma,
                                                        const float* __restrict__ beta) {
    __shared__ float r_sum[1024];
    __shared__ float r_sq [1024];
    const int tid = threadIdx.x;
    const int c = tid & 127;
    const int s = tid >> 7;
    float sum = 0.f, sq = 0.f;
    #pragma unroll 8
    for (int b = s; b < NBLK_STATS; b += 8) {
        sum += g_psum[b * 128 + c];
        sq  += g_psq [b * 128 + c];
    }
    r_sum[tid] = sum;
    r_sq [tid] = sq;
    __syncthreads();
    if (tid < 128) {
        float S = 0.f, Q = 0.f;
        #pragma unroll
        for (int j = 0; j < 8; ++j) { S += r_sum[j * 128 + c]; Q += r_sq[j * 128 + c]; }
        const float inv_n = 1.0f / (float)R_TOTAL;
        float mean = S * inv_n;
        float var  = Q * inv_n - mean * mean;
        float sc   = gamma[c] * rsqrtf(var + BN_EPS);
        g_scale[c] = sc;
        g_shift[c] = beta[c] - mean * sc;
    }
}

// ---------------------------------------------------------------------------
// Kernel 2b: permute weights into fp16 m16n8k16 B-fragment order
// ---------------------------------------------------------------------------
__global__ void permute_weights(const float* __restrict__ wqkv,
                                const float* __restrict__ wout) {
    int idx = blockIdx.x * 256 + threadIdx.x;     // 12288 total
    {
        int lane = idx & 31;
        int kst  = (idx >> 5) & 7;
        int nt   = idx >> 8;                      // 0..47
        int tig = lane & 3, gid = lane >> 2;
        int k0 = kst * 16 + 2 * tig;
        int n  = nt * 8 + gid;
        uint2 v;
        v.x = pkh2(wqkv[k0 * 384 + n],       wqkv[(k0 + 1) * 384 + n]);
        v.y = pkh2(wqkv[(k0 + 8) * 384 + n], wqkv[(k0 + 9) * 384 + n]);
        g_wqkv16[idx] = v;
    }
    if (idx < 16 * 8 * 32) {
        int lane = idx & 31;
        int kst  = (idx >> 5) & 7;
        int nt   = idx >> 8;                      // 0..15
        int tig = lane & 3, gid = lane >> 2;
        int k0 = kst * 16 + 2 * tig;
        int n  = nt * 8 + gid;
        uint2 v;
        v.x = pkh2(wout[k0 * 128 + n],       wout[(k0 + 1) * 128 + n]);
        v.y = pkh2(wout[(k0 + 8) * 128 + n], wout[(k0 + 9) * 128 + n]);
        g_wout16[idx] = v;
    }
}

// ---------------------------------------------------------------------------
// Kernel 3: fused BN-normalize -> QKV (fp16 mma) -> attention -> out-proj
// smem floats: sy16 5120 | qh 5376 | kh 5376 | vv 12032 | small 512 = 111 KB
// ---------------------------------------------------------------------------
#define QH_BLK   168                        // per-pair q/k stride in halves (21x16B, odd)
#define V_BLK    188                        // per-pair v stride in floats (47x16B, odd)
#define SY_U32   (MT * 8 * 128)             // 5120
#define SMEM_FLOATS (SY_U32 + 2 * (64 * QH_BLK / 2) + 64 * V_BLK + 512)
#define SMEM_BYTES  (SMEM_FLOATS * 4)

__global__ void __launch_bounds__(256, 2)
main_kernel(const float* __restrict__ x,
            const float* __restrict__ b_out,
            const float* __restrict__ mask,
            float* __restrict__ out) {
    extern __shared__ float sm[];
    unsigned* sy16 = (unsigned*)sm;               // [mt][kst][lane^kst][4 regs]
    unsigned short* qh = (unsigned short*)(sm + SY_U32);
    unsigned short* kh = qh + 64 * QH_BLK;
    float* vv      = sm + SY_U32 + (64 * QH_BLK);      // 2 halves = 1 float
    float* s_scale = vv + 64 * V_BLK;
    float* s_shift = s_scale + 128;
    float* s_mask  = s_shift + 128;
    float* s_bout  = s_mask + 128;

    const int tid  = threadIdx.x;
    const int lane = tid & 31;
    const int wrp  = tid >> 5;
    const int tig  = lane & 3;
    const int gid  = lane >> 2;
    const int row0 = blockIdx.x * ROWS;

    if (tid < 128) {
        s_scale[tid] = g_scale[tid];
        s_shift[tid] = g_shift[tid];
        s_bout [tid] = b_out[tid];
    }
    if (tid < 100) s_mask[tid] = mask[tid];
    __syncthreads();

    // ---- Phase 1: load + BN-normalize x into fp16 A-fragment sy (no pad) ---
    {
        const float4* x4  = (const float4*)x;
        const float4* sc4 = (const float4*)s_scale;
        const float4* sh4 = (const float4*)s_shift;
        #pragma unroll
        for (int f = tid; f < MT * 16 * 32; f += 256) {
            int r = f >> 5, c4 = f & 31;
            float4 v = x4[(size_t)(row0 + r) * 32 + c4];
            float4 sc = sc4[c4], sh = sh4[c4];
            float e0 = fmaf(v.x, sc.x, sh.x);
            float e1 = fmaf(v.y, sc.y, sh.y);
            float e2 = fmaf(v.z, sc.z, sh.z);
            float e3 = fmaf(v.w, sc.w, sh.w);
            int m = r >> 4, rr = r & 15;
            int g = rr & 7, rbit = rr >> 3;
            int kst = c4 >> 2;
            int kc  = 4 * (c4 & 3);
            int t   = (kc & 7) >> 1;
            int ri  = rbit + (kc >= 8 ? 2 : 0);
            unsigned* base = sy16 + (m * 8 + kst) * 128;
            base[((g * 4 + t)     ^ kst) * 4 + ri] = pkh2(e0, e1);
            base[((g * 4 + t + 1) ^ kst) * 4 + ri] = pkh2(e2, e3);
        }
    }
    __syncthreads();

    // ---- Phase 2: QKV GEMM via fp16 mma; warp owns 6 n-tiles, 2 passes of 3
    {
        #pragma unroll
        for (int pass = 0; pass < 2; ++pass) {
            const int nt0 = 6 * wrp + 3 * pass;
            float acc[MT][3][4];
            #pragma unroll
            for (int m = 0; m < MT; ++m)
                #pragma unroll
                for (int n = 0; n < 3; ++n)
                    #pragma unroll
                    for (int e = 0; e < 4; ++e) acc[m][n][e] = 0.f;

            const uint2* gwp = g_wqkv16 + nt0 * 8 * 32 + lane;
            #pragma unroll 2
            for (int kst = 0; kst < 8; ++kst) {
                uint2 b[3];
                #pragma unroll
                for (int n = 0; n < 3; ++n)
                    b[n] = __ldg(gwp + (n * 8 + kst) * 32);
                const int lx = lane ^ kst;
                #pragma unroll
                for (int m = 0; m < MT; ++m) {
                    uint4 a = *(const uint4*)&sy16[(m * 8 + kst) * 128 + lx * 4];
                    #pragma unroll
                    for (int n = 0; n < 3; ++n)
                        mma_f16(acc[m][n][0], acc[m][n][1], acc[m][n][2], acc[m][n][3],
                                a.x, a.y, a.z, a.w, b[n].x, b[n].y);
                }
            }

            // scatter: q/k as half2 into qh/kh, v as float2 into vv
            #pragma unroll
            for (int m = 0; m < MT; ++m) {
                int R0 = m * 16 + gid;
                int li0 = R0 / 10, i0 = R0 - li0 * 10;
                int R1 = R0 + 8;
                int li1 = R1 / 10, i1 = R1 - li1 * 10;
                #pragma unroll
                for (int n = 0; n < 3; ++n) {
                    int Cn = (nt0 + n) * 8 + 2 * tig;
                    int sel = Cn >> 7;
                    int cc  = Cn & 127;
                    int h   = cc >> 4;
                    int dh  = cc & 15;
                    if (sel == 2) {
                        vv[(li0 * 8 + h) * V_BLK + i0 * 16 + dh]     = acc[m][n][0];
                        vv[(li0 * 8 + h) * V_BLK + i0 * 16 + dh + 1] = acc[m][n][1];
                        vv[(li1 * 8 + h) * V_BLK + i1 * 16 + dh]     = acc[m][n][2];
                        vv[(li1 * 8 + h) * V_BLK + i1 * 16 + dh + 1] = acc[m][n][3];
                    } else {
                        unsigned short* dst = sel ? kh : qh;
                        *(unsigned*)(dst + (li0 * 8 + h) * QH_BLK + i0 * 16 + dh) =
                            pkh2(acc[m][n][0], acc[m][n][1]);
                        *(unsigned*)(dst + (li1 * 8 + h) * QH_BLK + i1 * 16 + dh) =
                            pkh2(acc[m][n][2], acc[m][n][3]);
                    }
                }
            }
        }
    }
    __syncthreads();

    // ---- Phase 3: masked attention, 4 threads/(item,head), rows sub+{0,4,8}
    {
        const int pair = tid >> 2;          // 0..63 == li*8+h
        const int sub  = tid & 3;
        const int li = pair >> 3;
        const int h  = pair & 7;
        const unsigned short* qb = qh + pair * QH_BLK;
        const unsigned short* kb = kh + pair * QH_BLK;
        const float* vb = vv + pair * V_BLK;
        const int i0 = sub, i1 = sub + 4;
        const bool has3 = (sub < 2);
        const int i2 = has3 ? sub + 8 : sub;     // clamped; discarded if !has3

        uint4 q0a = *(const uint4*)(qb + i0 * 16), q0b = *(const uint4*)(qb + i0 * 16 + 8);
        uint4 q1a = *(const uint4*)(qb + i1 * 16), q1b = *(const uint4*)(qb + i1 * 16 + 8);
        uint4 q2a = *(const uint4*)(qb + i2 * 16), q2b = *(const uint4*)(qb + i2 * 16 + 8);

        float d0[10], d1[10], d2[10];
        float mx0 = -1e30f, mx1 = -1e30f, mx2 = -1e30f;
        #pragma unroll
        for (int j = 0; j < 10; ++j) {
            uint4 ka = *(const uint4*)(kb + j * 16);
            uint4 kbq = *(const uint4*)(kb + j * 16 + 8);
            float p0 = hdot16(q0a, q0b, ka, kbq) * 0.25f * s_mask[i0 * 10 + j];
            float p1 = hdot16(q1a, q1b, ka, kbq) * 0.25f * s_mask[i1 * 10 + j];
            float p2 = hdot16(q2a, q2b, ka, kbq) * 0.25f * s_mask[i2 * 10 + j];
            d0[j] = p0; mx0 = fmaxf(mx0, p0);
            d1[j] = p1; mx1 = fmaxf(mx1, p1);
            d2[j] = p2; mx2 = fmaxf(mx2, p2);
        }
        float s0 = 0.f, s1 = 0.f, s2 = 0.f;
        #pragma unroll
        for (int j = 0; j < 10; ++j) {
            d0[j] = __expf(d0[j] - mx0); s0 += d0[j];
            d1[j] = __expf(d1[j] - mx1); s1 += d1[j];
            d2[j] = __expf(d2[j] - mx2); s2 += d2[j];
        }
        const float inv0 = 1.0f / s0, inv1 = 1.0f / s1, inv2 = 1.0f / s2;

        float o0[16], o1[16], o2[16];
        #pragma unroll
        for (int t = 0; t < 16; ++t) { o0[t] = 0.f; o1[t] = 0.f; o2[t] = 0.f; }
        #pragma unroll
        for (int j = 0; j < 10; ++j) {
            float a0 = d0[j] * inv0;
            float a1 = d1[j] * inv1;
            float a2 = d2[j] * inv2;
            #pragma unroll
            for (int t = 0; t < 4; ++t) {
                float4 v = *(const float4*)&vb[j * 16 + t * 4];
                o0[t * 4 + 0] = fmaf(a0, v.x, o0[t * 4 + 0]);
                o0[t * 4 + 1] = fmaf(a0, v.y, o0[t * 4 + 1]);
                o0[t * 4 + 2] = fmaf(a0, v.z, o0[t * 4 + 2]);
                o0[t * 4 + 3] = fmaf(a0, v.w, o0[t * 4 + 3]);
                o1[t * 4 + 0] = fmaf(a1, v.x, o1[t * 4 + 0]);
                o1[t * 4 + 1] = fmaf(a1, v.y, o1[t * 4 + 1]);
                o1[t * 4 + 2] = fmaf(a1, v.z, o1[t * 4 + 2]);
                o1[t * 4 + 3] = fmaf(a1, v.w, o1[t * 4 + 3]);
                o2[t * 4 + 0] = fmaf(a2, v.x, o2[t * 4 + 0]);
                o2[t * 4 + 1] = fmaf(a2, v.y, o2[t * 4 + 1]);
                o2[t * 4 + 2] = fmaf(a2, v.z, o2[t * 4 + 2]);
                o2[t * 4 + 3] = fmaf(a2, v.w, o2[t * 4 + 3]);
            }
        }

        // scatter rows as fp16 fragments: channels h*16+c -> tile (m, kst=h)
        #pragma unroll
        for (int rep = 0; rep < 3; ++rep) {
            if (rep == 2 && !has3) break;
            const float* o = rep == 0 ? o0 : (rep == 1 ? o1 : o2);
            int i = rep == 0 ? i0 : (rep == 1 ? i1 : i2);
            int R = li * 10 + i;
            int m = R >> 4, rr = R & 15;
            int g = rr & 7, rbit = rr >> 3;
            unsigned* base = sy16 + (m * 8 + h) * 128;
            #pragma unroll
            for (int t = 0; t < 4; ++t) {
                int ln = ((g * 4 + t) ^ h) * 4;
                base[ln + rbit]     = pkh2(o[2 * t],     o[2 * t + 1]);
                base[ln + rbit + 2] = pkh2(o[2 * t + 8], o[2 * t + 9]);
            }
        }
    }
    __syncthreads();

    // ---- Phase 4: out projection via fp16 mma. Warp w owns n-tiles 2w,2w+1 -
    {
        float acc[MT][2][4];
        #pragma unroll
        for (int m = 0; m < MT; ++m)
            #pragma unroll
            for (int n = 0; n < 2; ++n)
                #pragma unroll
                for (int e = 0; e < 4; ++e) acc[m][n][e] = 0.f;

        const int nt0 = 2 * wrp;
        const uint2* gwp = g_wout16 + nt0 * 8 * 32 + lane;

        #pragma unroll 4
        for (int kst = 0; kst < 8; ++kst) {
            uint2 b[2];
            #pragma unroll
            for (int n = 0; n < 2; ++n)
                b[n] = __ldg(gwp + (n * 8 + kst) * 32);
            const int lx = lane ^ kst;
            #pragma unroll
            for (int m = 0; m < MT; ++m) {
                uint4 a = *(const uint4*)&sy16[(m * 8 + kst) * 128 + lx * 4];
                #pragma unroll
                for (int n = 0; n < 2; ++n)
                    mma_f16(acc[m][n][0], acc[m][n][1], acc[m][n][2], acc[m][n][3],
                            a.x, a.y, a.z, a.w, b[n].x, b[n].y);
            }
        }

        #pragma unroll
        for (int m = 0; m < MT; ++m)
            #pragma unroll
            for (int n = 0; n < 2; ++n) {
                int col = (nt0 + n) * 8 + 2 * tig;
                float b0 = s_bout[col], b1 = s_bout[col + 1];
                int R0 = m * 16 + gid;
                *(float2*)&out[(size_t)(row0 + R0) * 128 + col] =
                    make_float2(acc[m][n][0] + b0, acc[m][n][1] + b1);
                *(float2*)&out[(size_t)(row0 + R0 + 8) * 128 + col] =
                    make_float2(acc[m][n][2] + b0, acc[m][n][3] + b1);
            }
    }
}

// ---------------------------------------------------------------------------
extern "C" void kernel_launch(void* const* d_in, const int* in_sizes, int n_in,
                              void* d_out, int out_size) {
    const float* x     = (const float*)d_in[0];
    const float* gamma = (const float*)d_in[1];
    const float* beta  = (const float*)d_in[2];
    const float* w_qkv = (const float*)d_in[3];
    const float* w_out = (const float*)d_in[4];
    const float* b_out = (const float*)d_in[5];
    const float* mask  = (const float*)d_in[6];
    float* out = (float*)d_out;

    cudaFuncSetAttribute(main_kernel,
                         cudaFuncAttributeMaxDynamicSharedMemorySize, SMEM_BYTES);

    stats_kernel<<<NBLK_STATS, 256>>>((const float4*)x);
    permute_weights<<<48, 256>>>(w_qkv, w_out);
    finalize_kernel<<<1, 1024>>>(gamma, beta);
    main_kernel<<<BTOT / NB, 256, SMEM_BYTES>>>(x, b_out, mask, out);
}

// round 7
// speedup vs baseline: 5.6238x; 1.0478x over previous
#include <cuda_runtime.h>
#include <cuda_fp16.h>

// ---------------------------------------------------------------------------
// Problem constants
#define R_TOTAL   327680          // N*T*VN rows
#define BTOT      32768           // N*T graph items
#define NB        8               // items per block
#define ROWS      (NB*10)         // 80 rows per block = 5 m-tiles, NO padding
#define MT        5               // m-tiles
#define NBLK_STATS 2048
#define BN_EPS    1e-5f

// Scratch (allocation-free)
__device__ float g_psum[NBLK_STATS * 128];
__device__ float g_psq [NBLK_STATS * 128];
__device__ float g_scale[128];
__device__ float g_shift[128];
// Pre-permuted fp16 weights in m16n8k16 B-fragment order:
// [nt][kst(8)][lane(32)] -> uint2 {b0 = W[k0,k0+1][n], b1 = W[k0+8,k0+9][n]}
__device__ uint2 g_wqkv16[48 * 8 * 32];
__device__ uint2 g_wout16[16 * 8 * 32];

// ---------------------------------------------------------------------------
__device__ __forceinline__ unsigned pkh2(float a, float b) {
    __half2 h = __floats2half2_rn(a, b);
    return *(unsigned*)&h;
}
__device__ __forceinline__ __half2 u2h2(unsigned u) { return *(__half2*)&u; }

// fp32-accumulator fp16 mma
__device__ __forceinline__ void mma_f16(float& c0, float& c1, float& c2, float& c3,
                                        unsigned a0, unsigned a1, unsigned a2, unsigned a3,
                                        unsigned b0, unsigned b1) {
    asm volatile("mma.sync.aligned.m16n8k16.row.col.f32.f16.f16.f32 "
                 "{%0,%1,%2,%3}, {%4,%5,%6,%7}, {%8,%9}, {%0,%1,%2,%3};\n"
                 : "+f"(c0), "+f"(c1), "+f"(c2), "+f"(c3)
                 : "r"(a0), "r"(a1), "r"(a2), "r"(a3), "r"(b0), "r"(b1));
}

// fp16-accumulator fp16 mma (C/D packed half2 x2)
__device__ __forceinline__ void mma_f16acc(unsigned& c0, unsigned& c1,
                                           unsigned a0, unsigned a1, unsigned a2, unsigned a3,
                                           unsigned b0, unsigned b1) {
    asm volatile("mma.sync.aligned.m16n8k16.row.col.f16.f16.f16.f16 "
                 "{%0,%1}, {%2,%3,%4,%5}, {%6,%7}, {%0,%1};\n"
                 : "+r"(c0), "+r"(c1)
                 : "r"(a0), "r"(a1), "r"(a2), "r"(a3), "r"(b0), "r"(b1));
}

// half2 dot of 16 fp16 values (2x uint4), fp32 finish
__device__ __forceinline__ float hdot16(uint4 qa, uint4 qb, uint4 ka, uint4 kb) {
    __half2 s = __hmul2(u2h2(qa.x), u2h2(ka.x));
    s = __hfma2(u2h2(qa.y), u2h2(ka.y), s);
    s = __hfma2(u2h2(qa.z), u2h2(ka.z), s);
    s = __hfma2(u2h2(qa.w), u2h2(ka.w), s);
    s = __hfma2(u2h2(qb.x), u2h2(kb.x), s);
    s = __hfma2(u2h2(qb.y), u2h2(kb.y), s);
    s = __hfma2(u2h2(qb.z), u2h2(kb.z), s);
    s = __hfma2(u2h2(qb.w), u2h2(kb.w), s);
    float2 f = __half22float2(s);
    return f.x + f.y;
}

// ---------------------------------------------------------------------------
// Kernel 1: per-channel sum / sumsq partials (DRAM-bound, ~32us)
// ---------------------------------------------------------------------------
__global__ void __launch_bounds__(256) stats_kernel(const float4* __restrict__ x4) {
    __shared__ float s_sum[256][4];
    __shared__ float s_sq [256][4];
    const int tid  = threadIdx.x;
    const int lane = tid & 31;
    const int slot = tid >> 5;

    float4 sum = make_float4(0.f, 0.f, 0.f, 0.f);
    float4 sq  = make_float4(0.f, 0.f, 0.f, 0.f);

    int row = blockIdx.x * 8 + slot;
    const int stride = NBLK_STATS * 8;
    #pragma unroll 4
    for (int it = 0; it < R_TOTAL / stride; ++it) {
        float4 v = x4[(size_t)row * 32 + lane];
        sum.x += v.x; sum.y += v.y; sum.z += v.z; sum.w += v.w;
        sq.x += v.x * v.x; sq.y += v.y * v.y; sq.z += v.z * v.z; sq.w += v.w * v.w;
        row += stride;
    }
    s_sum[tid][0] = sum.x; s_sum[tid][1] = sum.y; s_sum[tid][2] = sum.z; s_sum[tid][3] = sum.w;
    s_sq [tid][0] = sq.x;  s_sq [tid][1] = sq.y;  s_sq [tid][2] = sq.z;  s_sq [tid][3] = sq.w;
    __syncthreads();
    for (int off = 128; off >= 32; off >>= 1) {
        if (tid < off) {
            #pragma unroll
            for (int j = 0; j < 4; ++j) {
                s_sum[tid][j] += s_sum[tid + off][j];
                s_sq [tid][j] += s_sq [tid + off][j];
            }
        }
        __syncthreads();
    }
    if (tid < 32) {
        #pragma unroll
        for (int j = 0; j < 4; ++j) {
            g_psum[blockIdx.x * 128 + tid * 4 + j] = s_sum[tid][j];
            g_psq [blockIdx.x * 128 + tid * 4 + j] = s_sq [tid][j];
        }
    }
}

// ---------------------------------------------------------------------------
// Kernel 2: finalize BN affine params (parallel)
// ---------------------------------------------------------------------------
__global__ void __launch_bounds__(1024) finalize_kernel(const float* __restrict__ gamma,
                                                        const float* __restrict__ beta) {
    __shared__ float r_sum[1024];
    __shared__ float r_sq [1024];
    const int tid = threadIdx.x;
    const int c = tid & 127;
    const int s = tid >> 7;
    float sum = 0.f, sq = 0.f;
    #pragma unroll 8
    for (int b = s; b < NBLK_STATS; b += 8) {
        sum += g_psum[b * 128 + c];
        sq  += g_psq [b * 128 + c];
    }
    r_sum[tid] = sum;
    r_sq [tid] = sq;
    __syncthreads();
    if (tid < 128) {
        float S = 0.f, Q = 0.f;
        #pragma unroll
        for (int j = 0; j < 8; ++j) { S += r_sum[j * 128 + c]; Q += r_sq[j * 128 + c]; }
        const float inv_n = 1.0f / (float)R_TOTAL;
        float mean = S * inv_n;
        float var  = Q * inv_n - mean * mean;
        float sc   = gamma[c] * rsqrtf(var + BN_EPS);
        g_scale[c] = sc;
        g_shift[c] = beta[c] - mean * sc;
    }
}

// ---------------------------------------------------------------------------
// Kernel 2b: permute weights into fp16 m16n8k16 B-fragment order
// ---------------------------------------------------------------------------
__global__ void permute_weights(const float* __restrict__ wqkv,
                                const float* __restrict__ wout) {
    int idx = blockIdx.x * 256 + threadIdx.x;     // 12288 total
    {
        int lane = idx & 31;
        int kst  = (idx >> 5) & 7;
        int nt   = idx >> 8;                      // 0..47
        int tig = lane & 3, gid = lane >> 2;
        int k0 = kst * 16 + 2 * tig;
        int n  = nt * 8 + gid;
        uint2 v;
        v.x = pkh2(wqkv[k0 * 384 + n],       wqkv[(k0 + 1) * 384 + n]);
        v.y = pkh2(wqkv[(k0 + 8) * 384 + n], wqkv[(k0 + 9) * 384 + n]);
        g_wqkv16[idx] = v;
    }
    if (idx < 16 * 8 * 32) {
        int lane = idx & 31;
        int kst  = (idx >> 5) & 7;
        int nt   = idx >> 8;                      // 0..15
        int tig = lane & 3, gid = lane >> 2;
        int k0 = kst * 16 + 2 * tig;
        int n  = nt * 8 + gid;
        uint2 v;
        v.x = pkh2(wout[k0 * 128 + n],       wout[(k0 + 1) * 128 + n]);
        v.y = pkh2(wout[(k0 + 8) * 128 + n], wout[(k0 + 9) * 128 + n]);
        g_wout16[idx] = v;
    }
}

// ---------------------------------------------------------------------------
// Kernel 3: fused BN-normalize -> QKV (fp16 mma) -> attention -> out-proj
// smem: sy16 20KB | qh/kh/vh fp16 21.5KB each | small 2KB = ~87KB, 2 blk/SM
// ---------------------------------------------------------------------------
#define QH_BLK   168                        // per-pair stride in halves
#define SY_U32   (MT * 8 * 128)             // 5120
#define SMEM_FLOATS (SY_U32 + 3 * (64 * QH_BLK / 2) + 512)
#define SMEM_BYTES  (SMEM_FLOATS * 4)

__global__ void __launch_bounds__(256, 2)
main_kernel(const float* __restrict__ x,
            const float* __restrict__ b_out,
            const float* __restrict__ mask,
            float* __restrict__ out) {
    extern __shared__ float sm[];
    unsigned* sy16 = (unsigned*)sm;               // [mt][kst][lane^kst][4 regs]
    unsigned short* qh = (unsigned short*)(sm + SY_U32);
    unsigned short* kh = qh + 64 * QH_BLK;
    unsigned short* vh = kh + 64 * QH_BLK;
    float* s_scale = sm + SY_U32 + 3 * (64 * QH_BLK / 2);
    float* s_shift = s_scale + 128;
    float* s_mask  = s_shift + 128;
    float* s_bout  = s_mask + 128;

    const int tid  = threadIdx.x;
    const int lane = tid & 31;
    const int wrp  = tid >> 5;
    const int tig  = lane & 3;
    const int gid  = lane >> 2;
    const int row0 = blockIdx.x * ROWS;

    if (tid < 128) {
        s_scale[tid] = g_scale[tid];
        s_shift[tid] = g_shift[tid];
        s_bout [tid] = b_out[tid];
    }
    if (tid < 100) s_mask[tid] = mask[tid];
    __syncthreads();

    // ---- Phase 1: load + BN-normalize x into fp16 A-fragment sy (no pad) ---
    {
        const float4* x4  = (const float4*)x;
        const float4* sc4 = (const float4*)s_scale;
        const float4* sh4 = (const float4*)s_shift;
        #pragma unroll
        for (int f = tid; f < MT * 16 * 32; f += 256) {
            int r = f >> 5, c4 = f & 31;
            float4 v = x4[(size_t)(row0 + r) * 32 + c4];
            float4 sc = sc4[c4], sh = sh4[c4];
            float e0 = fmaf(v.x, sc.x, sh.x);
            float e1 = fmaf(v.y, sc.y, sh.y);
            float e2 = fmaf(v.z, sc.z, sh.z);
            float e3 = fmaf(v.w, sc.w, sh.w);
            int m = r >> 4, rr = r & 15;
            int g = rr & 7, rbit = rr >> 3;
            int kst = c4 >> 2;
            int kc  = 4 * (c4 & 3);
            int t   = (kc & 7) >> 1;
            int ri  = rbit + (kc >= 8 ? 2 : 0);
            unsigned* base = sy16 + (m * 8 + kst) * 128;
            base[((g * 4 + t)     ^ kst) * 4 + ri] = pkh2(e0, e1);
            base[((g * 4 + t + 1) ^ kst) * 4 + ri] = pkh2(e2, e3);
        }
    }
    __syncthreads();

    // ---- Phase 2: QKV GEMM, SINGLE pass. Warp w: qk n-tiles {4w..4w+3}
    //      (fp16 accumulators; logits tiny so q/k precision is uncritical)
    //      + v n-tiles {32+2w, 32+2w+1} (fp32 accumulators)
    {
        unsigned qkacc[MT][4][2];
        float    vacc [MT][2][4];
        #pragma unroll
        for (int m = 0; m < MT; ++m) {
            #pragma unroll
            for (int n = 0; n < 4; ++n) { qkacc[m][n][0] = 0u; qkacc[m][n][1] = 0u; }
            #pragma unroll
            for (int n = 0; n < 2; ++n)
                #pragma unroll
                for (int e = 0; e < 4; ++e) vacc[m][n][e] = 0.f;
        }

        const uint2* gqk = g_wqkv16 + (4 * wrp) * 8 * 32 + lane;
        const uint2* gv  = g_wqkv16 + (32 + 2 * wrp) * 8 * 32 + lane;

        #pragma unroll 2
        for (int kst = 0; kst < 8; ++kst) {
            uint2 bqk[4], bv[2];
            #pragma unroll
            for (int n = 0; n < 4; ++n) bqk[n] = __ldg(gqk + (n * 8 + kst) * 32);
            #pragma unroll
            for (int n = 0; n < 2; ++n) bv[n]  = __ldg(gv  + (n * 8 + kst) * 32);
            const int lx = lane ^ kst;
            #pragma unroll
            for (int m = 0; m < MT; ++m) {
                uint4 a = *(const uint4*)&sy16[(m * 8 + kst) * 128 + lx * 4];
                #pragma unroll
                for (int n = 0; n < 4; ++n)
                    mma_f16acc(qkacc[m][n][0], qkacc[m][n][1],
                               a.x, a.y, a.z, a.w, bqk[n].x, bqk[n].y);
                #pragma unroll
                for (int n = 0; n < 2; ++n)
                    mma_f16(vacc[m][n][0], vacc[m][n][1], vacc[m][n][2], vacc[m][n][3],
                            a.x, a.y, a.z, a.w, bv[n].x, bv[n].y);
            }
        }

        // scatter (all half2 stores, no cvt for q/k)
        #pragma unroll
        for (int m = 0; m < MT; ++m) {
            int R0 = m * 16 + gid;
            int li0 = R0 / 10, i0 = R0 - li0 * 10;
            int R1 = R0 + 8;
            int li1 = R1 / 10, i1 = R1 - li1 * 10;
            #pragma unroll
            for (int n = 0; n < 4; ++n) {
                int Cn = (4 * wrp + n) * 8 + 2 * tig;
                int sel = Cn >> 7;
                int cc  = Cn & 127;
                int h   = cc >> 4;
                int dh  = cc & 15;
                unsigned short* dst = sel ? kh : qh;
                *(unsigned*)(dst + (li0 * 8 + h) * QH_BLK + i0 * 16 + dh) = qkacc[m][n][0];
                *(unsigned*)(dst + (li1 * 8 + h) * QH_BLK + i1 * 16 + dh) = qkacc[m][n][1];
            }
            #pragma unroll
            for (int n = 0; n < 2; ++n) {
                int cc = (2 * wrp + n) * 8 + 2 * tig;
                int h  = cc >> 4;
                int dh = cc & 15;
                *(unsigned*)(vh + (li0 * 8 + h) * QH_BLK + i0 * 16 + dh) =
                    pkh2(vacc[m][n][0], vacc[m][n][1]);
                *(unsigned*)(vh + (li1 * 8 + h) * QH_BLK + i1 * 16 + dh) =
                    pkh2(vacc[m][n][2], vacc[m][n][3]);
            }
        }
    }
    __syncthreads();

    // ---- Phase 3: masked attention, 4 threads/(item,head), rows sub+{0,4,8}
    //      No max-subtraction (logits bounded << 10). V fp16, fp32 o-accum.
    {
        const int pair = tid >> 2;          // 0..63 == li*8+h
        const int sub  = tid & 3;
        const int li = pair >> 3;
        const int h  = pair & 7;
        const unsigned short* qb = qh + pair * QH_BLK;
        const unsigned short* kb = kh + pair * QH_BLK;
        const unsigned short* vb = vh + pair * QH_BLK;
        const int i0 = sub, i1 = sub + 4;
        const bool has3 = (sub < 2);
        const int i2 = has3 ? sub + 8 : sub;

        uint4 q0a = *(const uint4*)(qb + i0 * 16), q0b = *(const uint4*)(qb + i0 * 16 + 8);
        uint4 q1a = *(const uint4*)(qb + i1 * 16), q1b = *(const uint4*)(qb + i1 * 16 + 8);
        uint4 q2a = *(const uint4*)(qb + i2 * 16), q2b = *(const uint4*)(qb + i2 * 16 + 8);

        float d0[10], d1[10], d2[10];
        float s0 = 0.f, s1 = 0.f, s2 = 0.f;
        #pragma unroll
        for (int j = 0; j < 10; ++j) {
            uint4 ka = *(const uint4*)(kb + j * 16);
            uint4 kq = *(const uint4*)(kb + j * 16 + 8);
            float p0 = hdot16(q0a, q0b, ka, kq) * 0.25f * s_mask[i0 * 10 + j];
            float p1 = hdot16(q1a, q1b, ka, kq) * 0.25f * s_mask[i1 * 10 + j];
            float p2 = hdot16(q2a, q2b, ka, kq) * 0.25f * s_mask[i2 * 10 + j];
            d0[j] = __expf(p0); s0 += d0[j];
            d1[j] = __expf(p1); s1 += d1[j];
            d2[j] = __expf(p2); s2 += d2[j];
        }
        const float inv0 = 1.0f / s0, inv1 = 1.0f / s1, inv2 = 1.0f / s2;

        float o0[16], o1[16], o2[16];
        #pragma unroll
        for (int t = 0; t < 16; ++t) { o0[t] = 0.f; o1[t] = 0.f; o2[t] = 0.f; }
        #pragma unroll
        for (int j = 0; j < 10; ++j) {
            float a0 = d0[j] * inv0;
            float a1 = d1[j] * inv1;
            float a2 = d2[j] * inv2;
            uint4 va = *(const uint4*)(vb + j * 16);
            uint4 vq = *(const uint4*)(vb + j * 16 + 8);
            unsigned vr[8] = {va.x, va.y, va.z, va.w, vq.x, vq.y, vq.z, vq.w};
            #pragma unroll
            for (int t = 0; t < 8; ++t) {
                float2 f = __half22float2(u2h2(vr[t]));
                o0[2 * t]     = fmaf(a0, f.x, o0[2 * t]);
                o0[2 * t + 1] = fmaf(a0, f.y, o0[2 * t + 1]);
                o1[2 * t]     = fmaf(a1, f.x, o1[2 * t]);
                o1[2 * t + 1] = fmaf(a1, f.y, o1[2 * t + 1]);
                o2[2 * t]     = fmaf(a2, f.x, o2[2 * t]);
                o2[2 * t + 1] = fmaf(a2, f.y, o2[2 * t + 1]);
            }
        }

        // scatter rows as fp16 fragments: channels h*16+c -> tile (m, kst=h)
        #pragma unroll
        for (int rep = 0; rep < 3; ++rep) {
            if (rep == 2 && !has3) break;
            const float* o = rep == 0 ? o0 : (rep == 1 ? o1 : o2);
            int i = rep == 0 ? i0 : (rep == 1 ? i1 : i2);
            int R = li * 10 + i;
            int m = R >> 4, rr = R & 15;
            int g = rr & 7, rbit = rr >> 3;
            unsigned* base = sy16 + (m * 8 + h) * 128;
            #pragma unroll
            for (int t = 0; t < 4; ++t) {
                int ln = ((g * 4 + t) ^ h) * 4;
                base[ln + rbit]     = pkh2(o[2 * t],     o[2 * t + 1]);
                base[ln + rbit + 2] = pkh2(o[2 * t + 8], o[2 * t + 9]);
            }
        }
    }
    __syncthreads();

    // ---- Phase 4: out projection, warps 0-3 only, 4 n-tiles each (fp32 acc)
    if (wrp < 4) {
        float acc[MT][4][4];
        #pragma unroll
        for (int m = 0; m < MT; ++m)
            #pragma unroll
            for (int n = 0; n < 4; ++n)
                #pragma unroll
                for (int e = 0; e < 4; ++e) acc[m][n][e] = 0.f;

        const int nt0 = 4 * wrp;
        const uint2* gwp = g_wout16 + nt0 * 8 * 32 + lane;

        #pragma unroll 2
        for (int kst = 0; kst < 8; ++kst) {
            uint2 b[4];
            #pragma unroll
            for (int n = 0; n < 4; ++n)
                b[n] = __ldg(gwp + (n * 8 + kst) * 32);
            const int lx = lane ^ kst;
            #pragma unroll
            for (int m = 0; m < MT; ++m) {
                uint4 a = *(const uint4*)&sy16[(m * 8 + kst) * 128 + lx * 4];
                #pragma unroll
                for (int n = 0; n < 4; ++n)
                    mma_f16(acc[m][n][0], acc[m][n][1], acc[m][n][2], acc[m][n][3],
                            a.x, a.y, a.z, a.w, b[n].x, b[n].y);
            }
        }

        #pragma unroll
        for (int m = 0; m < MT; ++m)
            #pragma unroll
            for (int n = 0; n < 4; ++n) {
                int col = (nt0 + n) * 8 + 2 * tig;
                float b0 = s_bout[col], b1 = s_bout[col + 1];
                int R0 = m * 16 + gid;
                *(float2*)&out[(size_t)(row0 + R0) * 128 + col] =
                    make_float2(acc[m][n][0] + b0, acc[m][n][1] + b1);
                *(float2*)&out[(size_t)(row0 + R0 + 8) * 128 + col] =
                    make_float2(acc[m][n][2] + b0, acc[m][n][3] + b1);
            }
    }
}

// ---------------------------------------------------------------------------
extern "C" void kernel_launch(void* const* d_in, const int* in_sizes, int n_in,
                              void* d_out, int out_size) {
    const float* x     = (const float*)d_in[0];
    const float* gamma = (const float*)d_in[1];
    const float* beta  = (const float*)d_in[2];
    const float* w_qkv = (const float*)d_in[3];
    const float* w_out = (const float*)d_in[4];
    const float* b_out = (const float*)d_in[5];
    const float* mask  = (const float*)d_in[6];
    float* out = (float*)d_out;

    cudaFuncSetAttribute(main_kernel,
                         cudaFuncAttributeMaxDynamicSharedMemorySize, SMEM_BYTES);

    stats_kernel<<<NBLK_STATS, 256>>>((const float4*)x);
    permute_weights<<<48, 256>>>(w_qkv, w_out);
    finalize_kernel<<<1, 1024>>>(gamma, beta);
    main_kernel<<<BTOT / NB, 256, SMEM_BYTES>>>(x, b_out, mask, out);
}

// round 8
// speedup vs baseline: 5.8255x; 1.0359x over previous
#include <cuda_runtime.h>
#include <cuda_fp16.h>

// ---------------------------------------------------------------------------
// Problem constants
#define R_TOTAL   327680          // N*T*VN rows
#define BTOT      32768           // N*T graph items
#define NB        8               // items per block
#define ROWS      (NB*10)         // 80 rows per block = 5 m-tiles, NO padding
#define MT        5               // m-tiles
#define NBLK_STATS 2048
#define BN_EPS    1e-5f

// Scratch (allocation-free)
__device__ float g_psum[NBLK_STATS * 128];
__device__ float g_psq [NBLK_STATS * 128];
__device__ float g_scale[128];
__device__ float g_shift[128];
// Pre-permuted fp16 weights in m16n8k16 B-fragment order:
// [nt][kst(8)][lane(32)] -> uint2 {b0 = W[k0,k0+1][n], b1 = W[k0+8,k0+9][n]}
// q-part (nt 0..15) pre-scaled by 0.25 (the attention logit scale; exact pow2)
__device__ uint2 g_wqkv16[48 * 8 * 32];
__device__ uint2 g_wout16[16 * 8 * 32];

// ---------------------------------------------------------------------------
__device__ __forceinline__ unsigned pkh2(float a, float b) {
    __half2 h = __floats2half2_rn(a, b);
    return *(unsigned*)&h;
}
__device__ __forceinline__ __half2 u2h2(unsigned u) { return *(__half2*)&u; }

// fp32-accumulator fp16 mma
__device__ __forceinline__ void mma_f16(float& c0, float& c1, float& c2, float& c3,
                                        unsigned a0, unsigned a1, unsigned a2, unsigned a3,
                                        unsigned b0, unsigned b1) {
    asm volatile("mma.sync.aligned.m16n8k16.row.col.f32.f16.f16.f32 "
                 "{%0,%1,%2,%3}, {%4,%5,%6,%7}, {%8,%9}, {%0,%1,%2,%3};\n"
                 : "+f"(c0), "+f"(c1), "+f"(c2), "+f"(c3)
                 : "r"(a0), "r"(a1), "r"(a2), "r"(a3), "r"(b0), "r"(b1));
}

// fp16-accumulator fp16 mma (C/D packed half2 x2)
__device__ __forceinline__ void mma_f16acc(unsigned& c0, unsigned& c1,
                                           unsigned a0, unsigned a1, unsigned a2, unsigned a3,
                                           unsigned b0, unsigned b1) {
    asm volatile("mma.sync.aligned.m16n8k16.row.col.f16.f16.f16.f16 "
                 "{%0,%1}, {%2,%3,%4,%5}, {%6,%7}, {%0,%1};\n"
                 : "+r"(c0), "+r"(c1)
                 : "r"(a0), "r"(a1), "r"(a2), "r"(a3), "r"(b0), "r"(b1));
}

// packed fp32x2 ops (Blackwell FFMA2 — PTX-only)
#define FMA2(o, a, v) asm("fma.rn.f32x2 %0, %1, %2, %0;" : "+l"(o) : "l"(a), "l"(v))
#define MUL2(o, s)    asm("mul.rn.f32x2 %0, %0, %1;"     : "+l"(o) : "l"(s))
#define BCAST2(o, f)  asm("mov.b64 %0, {%1, %1};"        : "=l"(o) : "f"(f))
#define UNPK2(lo, hi, o) asm("mov.b64 {%0, %1}, %2;" : "=f"(lo), "=f"(hi) : "l"(o))

// half2 dot of 16 fp16 values (2x uint4), fp32 finish
__device__ __forceinline__ float hdot16(uint4 qa, uint4 qb, uint4 ka, uint4 kb) {
    __half2 s = __hmul2(u2h2(qa.x), u2h2(ka.x));
    s = __hfma2(u2h2(qa.y), u2h2(ka.y), s);
    s = __hfma2(u2h2(qa.z), u2h2(ka.z), s);
    s = __hfma2(u2h2(qa.w), u2h2(ka.w), s);
    s = __hfma2(u2h2(qb.x), u2h2(kb.x), s);
    s = __hfma2(u2h2(qb.y), u2h2(kb.y), s);
    s = __hfma2(u2h2(qb.z), u2h2(kb.z), s);
    s = __hfma2(u2h2(qb.w), u2h2(kb.w), s);
    float2 f = __half22float2(s);
    return f.x + f.y;
}

// ---------------------------------------------------------------------------
// Kernel 1: per-channel sum / sumsq partials (DRAM-bound, ~32us)
// ---------------------------------------------------------------------------
__global__ void __launch_bounds__(256) stats_kernel(const float4* __restrict__ x4) {
    __shared__ float s_sum[256][4];
    __shared__ float s_sq [256][4];
    const int tid  = threadIdx.x;
    const int lane = tid & 31;
    const int slot = tid >> 5;

    float4 sum = make_float4(0.f, 0.f, 0.f, 0.f);
    float4 sq  = make_float4(0.f, 0.f, 0.f, 0.f);

    int row = blockIdx.x * 8 + slot;
    const int stride = NBLK_STATS * 8;
    #pragma unroll 4
    for (int it = 0; it < R_TOTAL / stride; ++it) {
        float4 v = x4[(size_t)row * 32 + lane];
        sum.x += v.x; sum.y += v.y; sum.z += v.z; sum.w += v.w;
        sq.x += v.x * v.x; sq.y += v.y * v.y; sq.z += v.z * v.z; sq.w += v.w * v.w;
        row += stride;
    }
    s_sum[tid][0] = sum.x; s_sum[tid][1] = sum.y; s_sum[tid][2] = sum.z; s_sum[tid][3] = sum.w;
    s_sq [tid][0] = sq.x;  s_sq [tid][1] = sq.y;  s_sq [tid][2] = sq.z;  s_sq [tid][3] = sq.w;
    __syncthreads();
    for (int off = 128; off >= 32; off >>= 1) {
        if (tid < off) {
            #pragma unroll
            for (int j = 0; j < 4; ++j) {
                s_sum[tid][j] += s_sum[tid + off][j];
                s_sq [tid][j] += s_sq [tid + off][j];
            }
        }
        __syncthreads();
    }
    if (tid < 32) {
        #pragma unroll
        for (int j = 0; j < 4; ++j) {
            g_psum[blockIdx.x * 128 + tid * 4 + j] = s_sum[tid][j];
            g_psq [blockIdx.x * 128 + tid * 4 + j] = s_sq [tid][j];
        }
    }
}

// ---------------------------------------------------------------------------
// Kernel 2: finalize BN affine params (parallel)
// ---------------------------------------------------------------------------
__global__ void __launch_bounds__(1024) finalize_kernel(const float* __restrict__ gamma,
                                                        const float* __restrict__ beta) {
    __shared__ float r_sum[1024];
    __shared__ float r_sq [1024];
    const int tid = threadIdx.x;
    const int c = tid & 127;
    const int s = tid >> 7;
    float sum = 0.f, sq = 0.f;
    #pragma unroll 8
    for (int b = s; b < NBLK_STATS; b += 8) {
        sum += g_psum[b * 128 + c];
        sq  += g_psq [b * 128 + c];
    }
    r_sum[tid] = sum;
    r_sq [tid] = sq;
    __syncthreads();
    if (tid < 128) {
        float S = 0.f, Q = 0.f;
        #pragma unroll
        for (int j = 0; j < 8; ++j) { S += r_sum[j * 128 + c]; Q += r_sq[j * 128 + c]; }
        const float inv_n = 1.0f / (float)R_TOTAL;
        float mean = S * inv_n;
        float var  = Q * inv_n - mean * mean;
        float sc   = gamma[c] * rsqrtf(var + BN_EPS);
        g_scale[c] = sc;
        g_shift[c] = beta[c] - mean * sc;
    }
}

// ---------------------------------------------------------------------------
// Kernel 2b: permute weights into fp16 m16n8k16 B-fragment order.
// q-part (output cols < 128) pre-scaled by 0.25 (exact power of 2).
// ---------------------------------------------------------------------------
__global__ void permute_weights(const float* __restrict__ wqkv,
                                const float* __restrict__ wout) {
    int idx = blockIdx.x * 256 + threadIdx.x;     // 12288 total
    {
        int lane = idx & 31;
        int kst  = (idx >> 5) & 7;
        int nt   = idx >> 8;                      // 0..47
        int tig = lane & 3, gid = lane >> 2;
        int k0 = kst * 16 + 2 * tig;
        int n  = nt * 8 + gid;
        float s = (nt < 16) ? 0.25f : 1.0f;       // fold logit scale into Wq
        uint2 v;
        v.x = pkh2(s * wqkv[k0 * 384 + n],       s * wqkv[(k0 + 1) * 384 + n]);
        v.y = pkh2(s * wqkv[(k0 + 8) * 384 + n], s * wqkv[(k0 + 9) * 384 + n]);
        g_wqkv16[idx] = v;
    }
    if (idx < 16 * 8 * 32) {
        int lane = idx & 31;
        int kst  = (idx >> 5) & 7;
        int nt   = idx >> 8;                      // 0..15
        int tig = lane & 3, gid = lane >> 2;
        int k0 = kst * 16 + 2 * tig;
        int n  = nt * 8 + gid;
        uint2 v;
        v.x = pkh2(wout[k0 * 128 + n],       wout[(k0 + 1) * 128 + n]);
        v.y = pkh2(wout[(k0 + 8) * 128 + n], wout[(k0 + 9) * 128 + n]);
        g_wout16[idx] = v;
    }
}

// ---------------------------------------------------------------------------
// Kernel 3: fused BN-normalize -> QKV (fp16 mma) -> attention -> out-proj
// smem: sy16 20KB | qh/kh fp16 21KB each | vv fp32 41KB | small 2KB = ~107KB
// ---------------------------------------------------------------------------
#define QH_BLK   168                        // per-pair q/k stride in halves
#define V_BLK    164                        // per-pair v stride in floats
#define SY_U32   (MT * 8 * 128)             // 5120
#define SMEM_FLOATS (SY_U32 + 2 * (64 * QH_BLK / 2) + 64 * V_BLK + 512)
#define SMEM_BYTES  (SMEM_FLOATS * 4)

__global__ void __launch_bounds__(256, 2)
main_kernel(const float* __restrict__ x,
            const float* __restrict__ b_out,
            const float* __restrict__ mask,
            float* __restrict__ out) {
    extern __shared__ float sm[];
    unsigned* sy16 = (unsigned*)sm;               // [mt][kst][lane^kst][4 regs]
    unsigned short* qh = (unsigned short*)(sm + SY_U32);
    unsigned short* kh = qh + 64 * QH_BLK;
    float* vv      = sm + SY_U32 + (64 * QH_BLK); // after qh+kh (2*168*64 halves)
    float* s_scale = vv + 64 * V_BLK;
    float* s_shift = s_scale + 128;
    float* s_mask  = s_shift + 128;
    float* s_bout  = s_mask + 128;

    const int tid  = threadIdx.x;
    const int lane = tid & 31;
    const int wrp  = tid >> 5;
    const int tig  = lane & 3;
    const int gid  = lane >> 2;
    const int row0 = blockIdx.x * ROWS;

    if (tid < 128) {
        s_scale[tid] = g_scale[tid];
        s_shift[tid] = g_shift[tid];
        s_bout [tid] = b_out[tid];
    }
    if (tid < 100) s_mask[tid] = mask[tid];
    __syncthreads();

    // ---- Phase 1: load + BN-normalize x into fp16 A-fragment sy (no pad) ---
    {
        const float4* x4  = (const float4*)x;
        const float4* sc4 = (const float4*)s_scale;
        const float4* sh4 = (const float4*)s_shift;
        #pragma unroll
        for (int f = tid; f < MT * 16 * 32; f += 256) {
            int r = f >> 5, c4 = f & 31;
            float4 v = x4[(size_t)(row0 + r) * 32 + c4];
            float4 sc = sc4[c4], sh = sh4[c4];
            float e0 = fmaf(v.x, sc.x, sh.x);
            float e1 = fmaf(v.y, sc.y, sh.y);
            float e2 = fmaf(v.z, sc.z, sh.z);
            float e3 = fmaf(v.w, sc.w, sh.w);
            int m = r >> 4, rr = r & 15;
            int g = rr & 7, rbit = rr >> 3;
            int kst = c4 >> 2;
            int kc  = 4 * (c4 & 3);
            int t   = (kc & 7) >> 1;
            int ri  = rbit + (kc >= 8 ? 2 : 0);
            unsigned* base = sy16 + (m * 8 + kst) * 128;
            base[((g * 4 + t)     ^ kst) * 4 + ri] = pkh2(e0, e1);
            base[((g * 4 + t + 1) ^ kst) * 4 + ri] = pkh2(e2, e3);
        }
    }
    __syncthreads();

    // ---- Phase 2: QKV GEMM, SINGLE pass. Warp w: qk n-tiles {4w..4w+3}
    //      (fp16 accumulators) + v n-tiles {32+2w, 32+2w+1} (fp32 acc)
    {
        unsigned qkacc[MT][4][2];
        float    vacc [MT][2][4];
        #pragma unroll
        for (int m = 0; m < MT; ++m) {
            #pragma unroll
            for (int n = 0; n < 4; ++n) { qkacc[m][n][0] = 0u; qkacc[m][n][1] = 0u; }
            #pragma unroll
            for (int n = 0; n < 2; ++n)
                #pragma unroll
                for (int e = 0; e < 4; ++e) vacc[m][n][e] = 0.f;
        }

        const uint2* gqk = g_wqkv16 + (4 * wrp) * 8 * 32 + lane;
        const uint2* gv  = g_wqkv16 + (32 + 2 * wrp) * 8 * 32 + lane;

        #pragma unroll 2
        for (int kst = 0; kst < 8; ++kst) {
            uint2 bqk[4], bv[2];
            #pragma unroll
            for (int n = 0; n < 4; ++n) bqk[n] = __ldg(gqk + (n * 8 + kst) * 32);
            #pragma unroll
            for (int n = 0; n < 2; ++n) bv[n]  = __ldg(gv  + (n * 8 + kst) * 32);
            const int lx = lane ^ kst;
            #pragma unroll
            for (int m = 0; m < MT; ++m) {
                uint4 a = *(const uint4*)&sy16[(m * 8 + kst) * 128 + lx * 4];
                #pragma unroll
                for (int n = 0; n < 4; ++n)
                    mma_f16acc(qkacc[m][n][0], qkacc[m][n][1],
                               a.x, a.y, a.z, a.w, bqk[n].x, bqk[n].y);
                #pragma unroll
                for (int n = 0; n < 2; ++n)
                    mma_f16(vacc[m][n][0], vacc[m][n][1], vacc[m][n][2], vacc[m][n][3],
                            a.x, a.y, a.z, a.w, bv[n].x, bv[n].y);
            }
        }

        // scatter: q/k half2, v float2
        #pragma unroll
        for (int m = 0; m < MT; ++m) {
            int R0 = m * 16 + gid;
            int li0 = R0 / 10, i0 = R0 - li0 * 10;
            int R1 = R0 + 8;
            int li1 = R1 / 10, i1 = R1 - li1 * 10;
            #pragma unroll
            for (int n = 0; n < 4; ++n) {
                int Cn = (4 * wrp + n) * 8 + 2 * tig;
                int sel = Cn >> 7;
                int cc  = Cn & 127;
                int h   = cc >> 4;
                int dh  = cc & 15;
                unsigned short* dst = sel ? kh : qh;
                *(unsigned*)(dst + (li0 * 8 + h) * QH_BLK + i0 * 16 + dh) = qkacc[m][n][0];
                *(unsigned*)(dst + (li1 * 8 + h) * QH_BLK + i1 * 16 + dh) = qkacc[m][n][1];
            }
            #pragma unroll
            for (int n = 0; n < 2; ++n) {
                int cc = (2 * wrp + n) * 8 + 2 * tig;
                int h  = cc >> 4;
                int dh = cc & 15;
                *(float2*)&vv[(li0 * 8 + h) * V_BLK + i0 * 16 + dh] =
                    make_float2(vacc[m][n][0], vacc[m][n][1]);
                *(float2*)&vv[(li1 * 8 + h) * V_BLK + i1 * 16 + dh] =
                    make_float2(vacc[m][n][2], vacc[m][n][3]);
            }
        }
    }
    __syncthreads();

    // ---- Phase 3: masked attention, 4 threads/(item,head), rows sub+{0,4,8}
    //      fp16 dots, fp32 exp, packed-fp32x2 AV accumulation.
    {
        const int pair = tid >> 2;          // 0..63 == li*8+h
        const int sub  = tid & 3;
        const int li = pair >> 3;
        const int h  = pair & 7;
        const unsigned short* qb = qh + pair * QH_BLK;
        const unsigned short* kb = kh + pair * QH_BLK;
        const float* vb = vv + pair * V_BLK;
        const int i0 = sub, i1 = sub + 4;
        const bool has3 = (sub < 2);
        const int i2 = has3 ? sub + 8 : sub;

        uint4 q0a = *(const uint4*)(qb + i0 * 16), q0b = *(const uint4*)(qb + i0 * 16 + 8);
        uint4 q1a = *(const uint4*)(qb + i1 * 16), q1b = *(const uint4*)(qb + i1 * 16 + 8);
        uint4 q2a = *(const uint4*)(qb + i2 * 16), q2b = *(const uint4*)(qb + i2 * 16 + 8);

        float d0[10], d1[10], d2[10];
        float s0 = 0.f, s1 = 0.f, s2 = 0.f;
        #pragma unroll
        for (int j = 0; j < 10; ++j) {
            uint4 ka = *(const uint4*)(kb + j * 16);
            uint4 kq = *(const uint4*)(kb + j * 16 + 8);
            // 0.25 logit scale already folded into Wq
            float p0 = hdot16(q0a, q0b, ka, kq) * s_mask[i0 * 10 + j];
            float p1 = hdot16(q1a, q1b, ka, kq) * s_mask[i1 * 10 + j];
            float p2 = hdot16(q2a, q2b, ka, kq) * s_mask[i2 * 10 + j];
            d0[j] = __expf(p0); s0 += d0[j];
            d1[j] = __expf(p1); s1 += d1[j];
            d2[j] = __expf(p2); s2 += d2[j];
        }

        unsigned long long o0p[8], o1p[8], o2p[8];
        #pragma unroll
        for (int t = 0; t < 8; ++t) { o0p[t] = 0ull; o1p[t] = 0ull; o2p[t] = 0ull; }
        #pragma unroll
        for (int j = 0; j < 10; ++j) {
            unsigned long long pa0, pa1, pa2;
            BCAST2(pa0, d0[j]);
            BCAST2(pa1, d1[j]);
            BCAST2(pa2, d2[j]);
            const ulonglong2* vp = (const ulonglong2*)(vb + j * 16);
            ulonglong2 w0 = vp[0], w1 = vp[1], w2 = vp[2], w3 = vp[3];
            unsigned long long vr[8] = {w0.x, w0.y, w1.x, w1.y, w2.x, w2.y, w3.x, w3.y};
            #pragma unroll
            for (int t = 0; t < 8; ++t) {
                FMA2(o0p[t], pa0, vr[t]);
                FMA2(o1p[t], pa1, vr[t]);
                FMA2(o2p[t], pa2, vr[t]);
            }
        }
        // normalize by 1/sum (packed)
        {
            unsigned long long pi0, pi1, pi2;
            BCAST2(pi0, 1.0f / s0);
            BCAST2(pi1, 1.0f / s1);
            BCAST2(pi2, 1.0f / s2);
            #pragma unroll
            for (int t = 0; t < 8; ++t) {
                MUL2(o0p[t], pi0);
                MUL2(o1p[t], pi1);
                MUL2(o2p[t], pi2);
            }
        }

        // scatter rows as fp16 fragments: channels h*16+c -> tile (m, kst=h)
        #pragma unroll
        for (int rep = 0; rep < 3; ++rep) {
            if (rep == 2 && !has3) break;
            const unsigned long long* o = rep == 0 ? o0p : (rep == 1 ? o1p : o2p);
            int i = rep == 0 ? i0 : (rep == 1 ? i1 : i2);
            int R = li * 10 + i;
            int m = R >> 4, rr = R & 15;
            int g = rr & 7, rbit = rr >> 3;
            unsigned* base = sy16 + (m * 8 + h) * 128;
            #pragma unroll
            for (int t = 0; t < 4; ++t) {
                int ln = ((g * 4 + t) ^ h) * 4;
                float lo, hi, lo2, hi2;
                UNPK2(lo, hi, o[t]);
                UNPK2(lo2, hi2, o[t + 4]);
                base[ln + rbit]     = pkh2(lo, hi);
                base[ln + rbit + 2] = pkh2(lo2, hi2);
            }
        }
    }
    __syncthreads();

    // ---- Phase 4: out projection, all 8 warps, 2 n-tiles each (fp32 acc) ---
    {
        float acc[MT][2][4];
        #pragma unroll
        for (int m = 0; m < MT; ++m)
            #pragma unroll
            for (int n = 0; n < 2; ++n)
                #pragma unroll
                for (int e = 0; e < 4; ++e) acc[m][n][e] = 0.f;

        const int nt0 = 2 * wrp;
        const uint2* gwp = g_wout16 + nt0 * 8 * 32 + lane;

        #pragma unroll 4
        for (int kst = 0; kst < 8; ++kst) {
            uint2 b[2];
            #pragma unroll
            for (int n = 0; n < 2; ++n)
                b[n] = __ldg(gwp + (n * 8 + kst) * 32);
            const int lx = lane ^ kst;
            #pragma unroll
            for (int m = 0; m < MT; ++m) {
                uint4 a = *(const uint4*)&sy16[(m * 8 + kst) * 128 + lx * 4];
                #pragma unroll
                for (int n = 0; n < 2; ++n)
                    mma_f16(acc[m][n][0], acc[m][n][1], acc[m][n][2], acc[m][n][3],
                            a.x, a.y, a.z, a.w, b[n].x, b[n].y);
            }
        }

        #pragma unroll
        for (int m = 0; m < MT; ++m)
            #pragma unroll
            for (int n = 0; n < 2; ++n) {
                int col = (nt0 + n) * 8 + 2 * tig;
                float b0 = s_bout[col], b1 = s_bout[col + 1];
                int R0 = m * 16 + gid;
                *(float2*)&out[(size_t)(row0 + R0) * 128 + col] =
                    make_float2(acc[m][n][0] + b0, acc[m][n][1] + b1);
                *(float2*)&out[(size_t)(row0 + R0 + 8) * 128 + col] =
                    make_float2(acc[m][n][2] + b0, acc[m][n][3] + b1);
            }
    }
}

// ---------------------------------------------------------------------------
extern "C" void kernel_launch(void* const* d_in, const int* in_sizes, int n_in,
                              void* d_out, int out_size) {
    const float* x     = (const float*)d_in[0];
    const float* gamma = (const float*)d_in[1];
    const float* beta  = (const float*)d_in[2];
    const float* w_qkv = (const float*)d_in[3];
    const float* w_out = (const float*)d_in[4];
    const float* b_out = (const float*)d_in[5];
    const float* mask  = (const float*)d_in[6];
    float* out = (float*)d_out;

    cudaFuncSetAttribute(main_kernel,
                         cudaFuncAttributeMaxDynamicSharedMemorySize, SMEM_BYTES);

    stats_kernel<<<NBLK_STATS, 256>>>((const float4*)x);
    permute_weights<<<48, 256>>>(w_qkv, w_out);
    finalize_kernel<<<1, 1024>>>(gamma, beta);
    main_kernel<<<BTOT / NB, 256, SMEM_BYTES>>>(x, b_out, mask, out);
}